// round 5
// baseline (speedup 1.0000x reference)
#include <cuda_runtime.h>
#include <cstdint>

#define BB    8
#define NN    4096
#define KNB   20
#define NPTS  (BB * NN)          /* 32768  */
#define M1    (NPTS * KNB)       /* 655360 */
#define EPSB  1e-5f

/* ================= static device scratch (no allocations) ============= */
__device__ int   g_idx[M1];                         /* knn indices          */
__device__ float g_h1[(size_t)M1 * 64];             /* h1 [M1,64]           */
__device__ float g_cat[(size_t)NPTS * 192];         /* [x1|x2] [P,192]      */
__device__ float g_w2t[64 * 128];                   /* W2^T [k][o]          */
__device__ float g_w3t[192 * 256];                  /* W3^T [k][o]          */
__device__ float g_fpart[640 * 27];                 /* feat gram partials   */
__device__ float g_colpart[64 * 8192];              /* h1 colsum partials   */
__device__ float g_gpart[(size_t)640 * 4096];       /* h1 gram partials     */
__device__ float g_gram[4096];                      /* h1 gram 64x64        */
__device__ float g_h1colsum[64];
__device__ float g_cpart[(size_t)128 * 36864];      /* cat gram partials    */
__device__ float g_cspart[128 * 192];               /* cat colsum partials  */
__device__ float g_cgram[36864];                    /* cat gram 192x192     */
__device__ float g_catsum[192];
__device__ float g_mu[448];                         /* L1:0 L2:64 L3:192    */
__device__ float g_rs[448];

/* ================= f32x2 packed-math helpers ========================= */
__device__ __forceinline__ double pack2(float x, float y) {
    double d;
    asm("mov.b64 %0, {%1, %2};" : "=d"(d) : "f"(x), "f"(y));
    return d;
}
__device__ __forceinline__ float2 unpack2(double d) {
    float2 r;
    asm("mov.b64 {%0, %1}, %2;" : "=f"(r.x), "=f"(r.y) : "d"(d));
    return r;
}
__device__ __forceinline__ double ffma2(double a, double b, double c) {
    double d;
    asm("fma.rn.f32x2 %0, %1, %2, %3;" : "=d"(d) : "d"(a), "d"(b), "d"(c));
    return d;
}

/* ================= prep: transpose W2, W3 ============================ */
__global__ void prep_kernel(const float* __restrict__ W2,
                            const float* __restrict__ W3) {
    int t = blockIdx.x * blockDim.x + threadIdx.x;
    if (t < 64 * 128) {
        int k = t / 128, o = t % 128;
        g_w2t[t] = W2[o * 64 + k];
    }
    if (t < 192 * 256) {
        int k = t / 256, o = t % 256;
        g_w3t[t] = W3[o * 192 + k];
    }
}

/* ================= kNN (unchanged, known-correct) ==================== */
#define KCHUNK 2048
__global__ void knn_kernel(const float* __restrict__ x) {
    __shared__ float4 pts[KCHUNK];
    const int b = blockIdx.x;
    const int n = blockIdx.y * blockDim.x + threadIdx.x;
    const float* xb = x + b * 3 * NN;
    const float qx = xb[n], qy = xb[NN + n], qz = xb[2 * NN + n];
    const float q2x = 2.f * qx, q2y = 2.f * qy, q2z = 2.f * qz;

    float bv[KNB];
    int   bi[KNB];
    float vmin;
    int   mp;

    for (int m = threadIdx.x; m < KCHUNK; m += blockDim.x) {
        float px = xb[m], py = xb[NN + m], pz = xb[2 * NN + m];
        pts[m] = make_float4(px, py, pz, fmaf(px, px, fmaf(py, py, pz * pz)));
    }
    __syncthreads();

#pragma unroll
    for (int m = 0; m < KNB; ++m) {
        float4 p = pts[m];
        bv[m] = fmaf(q2x, p.x, fmaf(q2y, p.y, fmaf(q2z, p.z, -p.w)));
        bi[m] = m;
    }
    vmin = bv[0]; mp = 0;
#pragma unroll
    for (int t = 1; t < KNB; ++t) if (bv[t] < vmin) { vmin = bv[t]; mp = t; }

    for (int m = KNB; m < KCHUNK; ++m) {
        float4 p = pts[m];
        float v = fmaf(q2x, p.x, fmaf(q2y, p.y, fmaf(q2z, p.z, -p.w)));
        if (v > vmin) {
            bv[mp] = v; bi[mp] = m;
            vmin = bv[0]; mp = 0;
#pragma unroll
            for (int t = 1; t < KNB; ++t) if (bv[t] < vmin) { vmin = bv[t]; mp = t; }
        }
    }
    for (int base = KCHUNK; base < NN; base += KCHUNK) {
        __syncthreads();
        for (int m = threadIdx.x; m < KCHUNK; m += blockDim.x) {
            float px = xb[base + m], py = xb[NN + base + m], pz = xb[2 * NN + base + m];
            pts[m] = make_float4(px, py, pz, fmaf(px, px, fmaf(py, py, pz * pz)));
        }
        __syncthreads();
        for (int m = 0; m < KCHUNK; ++m) {
            float4 p = pts[m];
            float v = fmaf(q2x, p.x, fmaf(q2y, p.y, fmaf(q2z, p.z, -p.w)));
            if (v > vmin) {
                bv[mp] = v; bi[mp] = base + m;
                vmin = bv[0]; mp = 0;
#pragma unroll
                for (int t = 1; t < KNB; ++t) if (bv[t] < vmin) { vmin = bv[t]; mp = t; }
            }
        }
    }
    int* op = g_idx + (size_t)(b * NN + n) * KNB;
#pragma unroll
    for (int t = 0; t < KNB; ++t) op[t] = bi[t];
}

/* ================= feat Gram (6x6 sym = 21) + feat colsum (6) ======== */
/* grid 640, 256 thr, 4 edges/thread.                                    */
__global__ void fgram_kernel(const float* __restrict__ x) {
    const int t = threadIdx.x;
    float s[27];
#pragma unroll
    for (int v = 0; v < 27; ++v) s[v] = 0.f;

    for (int e = 0; e < 4; ++e) {
        int m = blockIdx.x * 1024 + e * 256 + t;
        int p = m / KNB;
        int b = p >> 12, n = p & (NN - 1);
        const float* xb = x + b * 3 * NN;
        int nb = g_idx[m];
        float cx = xb[n], cy = xb[NN + n], cz = xb[2 * NN + n];
        float f[6];
        f[0] = xb[nb] - cx;
        f[1] = xb[NN + nb] - cy;
        f[2] = xb[2 * NN + nb] - cz;
        f[3] = cx; f[4] = cy; f[5] = cz;
        int u = 0;
#pragma unroll
        for (int i = 0; i < 6; ++i) {
            s[21 + i] += f[i];
#pragma unroll
            for (int j = 0; j <= i; ++j) s[u++] = fmaf(f[i], f[j], s[u]);
        }
    }
#pragma unroll
    for (int off = 16; off; off >>= 1)
#pragma unroll
        for (int v = 0; v < 27; ++v)
            s[v] += __shfl_xor_sync(0xffffffffu, s[v], off);

    __shared__ float sm[8][27];
    if ((t & 31) == 0)
#pragma unroll
        for (int v = 0; v < 27; ++v) sm[t >> 5][v] = s[v];
    __syncthreads();
    if (t < 27) {
        float a = 0.f;
#pragma unroll
        for (int w = 0; w < 8; ++w) a += sm[w][t];
        g_fpart[blockIdx.x * 27 + t] = a;
    }
}

/* ================= BN1 stats from feat Gram ========================== */
__global__ void bn1fin_kernel(const float* __restrict__ W1) {
    __shared__ float part[27][8];
    __shared__ float gf[27];
    const int t = threadIdx.x;
    if (t < 216) {
        int j = t / 8, sl = t % 8;
        float a = 0.f;
        for (int i = sl; i < 640; i += 8) a += g_fpart[i * 27 + j];
        part[j][sl] = a;
    }
    __syncthreads();
    if (t < 27) {
        float a = 0.f;
#pragma unroll
        for (int sl = 0; sl < 8; ++sl) a += part[t][sl];
        gf[t] = a;
    }
    __syncthreads();
    if (t < 64) {
        float w[6];
#pragma unroll
        for (int c = 0; c < 6; ++c) w[c] = W1[t * 6 + c];
        const float invM = 1.f / (float)M1;
        float mu = 0.f;
#pragma unroll
        for (int i = 0; i < 6; ++i) mu = fmaf(w[i], gf[21 + i], mu);
        mu *= invM;
        float q = 0.f;
#pragma unroll
        for (int i = 0; i < 6; ++i)
#pragma unroll
            for (int j = 0; j <= i; ++j) {
                float val = gf[i * (i + 1) / 2 + j];
                float c = w[i] * w[j] * val;
                q += (i == j) ? c : 2.f * c;
            }
        q *= invM;
        g_mu[t] = mu;
        g_rs[t] = rsqrtf(q - mu * mu + EPSB);
    }
}

/* ================= h1 = BN1(W1 feat)+ReLU, pool->x1, colsum ========== */
/* block 256 = (o:64, pl:4); grid NPTS/4 = 8192.                         */
__global__ void h1pool_kernel(const float* __restrict__ x,
                              const float* __restrict__ W1,
                              const float* __restrict__ g1,
                              const float* __restrict__ b1) {
    __shared__ float feat[80][6];
    __shared__ float red[4][64];
    const int t  = threadIdx.x;
    const int o  = t & 63;
    const int pl = t >> 6;

    if (t < 80) {
        int p = blockIdx.x * 4 + t / 20;
        int k = t % 20;
        int m = p * KNB + k;
        int b = p >> 12, n = p & (NN - 1);
        const float* xb = x + b * 3 * NN;
        int nb = g_idx[m];
        float cx = xb[n], cy = xb[NN + n], cz = xb[2 * NN + n];
        feat[t][0] = xb[nb] - cx;
        feat[t][1] = xb[NN + nb] - cy;
        feat[t][2] = xb[2 * NN + nb] - cz;
        feat[t][3] = cx; feat[t][4] = cy; feat[t][5] = cz;
    }
    __syncthreads();

    float wr[6];
#pragma unroll
    for (int c = 0; c < 6; ++c) wr[c] = W1[o * 6 + c];
    const float mu = g_mu[o], rs = g_rs[o], gg = g1[o], bb = b1[o];

    const int p = blockIdx.x * 4 + pl;
    float* hp = g_h1 + (size_t)p * KNB * 64 + o;

    float h[KNB];
    float hmax = 0.f, cs = 0.f;
#pragma unroll
    for (int k = 0; k < KNB; ++k) {
        const float* f = feat[pl * KNB + k];
        float y = wr[0] * f[0];
        y = fmaf(wr[1], f[1], y);
        y = fmaf(wr[2], f[2], y);
        y = fmaf(wr[3], f[3], y);
        y = fmaf(wr[4], f[4], y);
        y = fmaf(wr[5], f[5], y);
        float hv = fmaxf(fmaf((y - mu) * rs, gg, bb), 0.f);
        h[k] = hv;
        hp[(size_t)k * 64] = hv;
        hmax = fmaxf(hmax, hv);
        cs += hv;
    }
    float se = 0.f, sw = 0.f;
#pragma unroll
    for (int k = 0; k < KNB; ++k) {
        float e = __expf(h[k] - hmax);
        se += e;
        sw = fmaf(e, h[k], sw);
    }
    g_cat[(size_t)p * 192 + o] = sw / se;

    red[pl][o] = cs;
    __syncthreads();
    if (pl == 0)
        g_colpart[(size_t)o * 8192 + blockIdx.x] =
            red[0][o] + red[1][o] + red[2][o] + red[3][o];
}

/* ================= h1 Gram (64x64) per-block partials ================ */
/* grid 640 blocks x 1024 rows, chunks of 32.                            */
__global__ __launch_bounds__(256) void h1gram_kernel() {
    __shared__ float sm[32][68];
    const int t = threadIdx.x;
    const int i16 = t & 15, j16 = t >> 4;

    double acc[4][2];
#pragma unroll
    for (int i = 0; i < 4; ++i) { acc[i][0] = 0.0; acc[i][1] = 0.0; }

    for (int c = 0; c < 32; ++c) {
        const int rowbase = blockIdx.x * 1024 + c * 32;
#pragma unroll
        for (int l = 0; l < 2; ++l) {
            int q = t + 256 * l;
            int r = q >> 4, cq = (q & 15) << 2;
            float4 v = *(const float4*)(g_h1 + (size_t)(rowbase + r) * 64 + cq);
            *(float4*)&sm[r][cq] = v;
        }
        __syncthreads();
#pragma unroll 8
        for (int r = 0; r < 32; ++r) {
            float4 a = *(const float4*)&sm[r][i16 * 4];
            double b0 = *(const double*)&sm[r][j16 * 4];
            double b1 = *(const double*)&sm[r][j16 * 4 + 2];
            const float av[4] = {a.x, a.y, a.z, a.w};
#pragma unroll
            for (int i = 0; i < 4; ++i) {
                double a2 = pack2(av[i], av[i]);
                acc[i][0] = ffma2(a2, b0, acc[i][0]);
                acc[i][1] = ffma2(a2, b1, acc[i][1]);
            }
        }
        __syncthreads();
    }
    float* gp = g_gpart + (size_t)blockIdx.x * 4096;
#pragma unroll
    for (int i = 0; i < 4; ++i) {
        float2 c0 = unpack2(acc[i][0]);
        float2 c1 = unpack2(acc[i][1]);
        float4 v = make_float4(c0.x, c0.y, c1.x, c1.y);
        *(float4*)(gp + (i16 * 4 + i) * 64 + j16 * 4) = v;
    }
}

/* ================= reduce h1 gram + colsum =========================== */
__global__ void gram2fin_kernel() {
    __shared__ float red[64][4];
    const int t = threadIdx.x;
    const int e = t >> 2, sl = t & 3;
    if (blockIdx.x == 64) {
        float a = 0.f;
        for (int i = sl; i < 8192; i += 4) a += g_colpart[(size_t)e * 8192 + i];
        red[e][sl] = a;
        __syncthreads();
        if (sl == 0)
            g_h1colsum[e] = red[e][0] + red[e][1] + red[e][2] + red[e][3];
        return;
    }
    const int ge = blockIdx.x * 64 + e;
    float a = 0.f;
    for (int i = sl; i < 640; i += 4) a += g_gpart[(size_t)i * 4096 + ge];
    red[e][sl] = a;
    __syncthreads();
    if (sl == 0)
        g_gram[ge] = red[e][0] + red[e][1] + red[e][2] + red[e][3];
}

/* ================= BN2 stats from h1 Gram ============================ */
__global__ void bn2fin_kernel() {
    const int o = blockIdx.x;   /* 128 channels */
    const int i = threadIdx.x;  /* 64 */
    __shared__ float w[64], rq[64], rm[64];
    w[i] = g_w2t[i * 128 + o];
    __syncthreads();
    float qi = 0.f;
    const float* Gi = g_gram + i * 64;
#pragma unroll 8
    for (int j = 0; j < 64; ++j) qi = fmaf(Gi[j], w[j], qi);
    qi *= w[i];
    rq[i] = qi;
    rm[i] = w[i] * g_h1colsum[i];
    __syncthreads();
    for (int s = 32; s > 0; s >>= 1) {
        if (i < s) { rq[i] += rq[i + s]; rm[i] += rm[i + s]; }
        __syncthreads();
    }
    if (i == 0) {
        const float invM = 1.f / (float)M1;
        float mu = rm[0] * invM;
        float var = rq[0] * invM - mu * mu;
        g_mu[64 + o] = mu;
        g_rs[64 + o] = rsqrtf(var + EPSB);
    }
}

/* ================= GEMM2 + BN2 + ReLU + softmax pool -> x2 =========== */
/* C[160,128] tiles: 8 points x 20 nbrs; 256 thr, 10x8 micro, f32x2.     */
__global__ __launch_bounds__(256) void gemm2pool_kernel(
        const float* __restrict__ g2, const float* __restrict__ b2v) {
    __shared__ float As[32][164];
    __shared__ float Bs[32][128];
    const int t = threadIdx.x;
    const int tx = t & 15, ty = t >> 4;
    const int mbase = blockIdx.x * 160;

    double acc[10][4];
#pragma unroll
    for (int i = 0; i < 10; ++i)
#pragma unroll
        for (int j = 0; j < 4; ++j) acc[i][j] = 0.0;

#pragma unroll
    for (int kt = 0; kt < 64; kt += 32) {
#pragma unroll
        for (int l = 0; l < 5; ++l) {
            int q = t + 256 * l;
            int r = q >> 3, kq = (q & 7) << 2;
            float4 v = *(const float4*)(g_h1 + (size_t)(mbase + r) * 64 + kt + kq);
            As[kq + 0][r] = v.x;
            As[kq + 1][r] = v.y;
            As[kq + 2][r] = v.z;
            As[kq + 3][r] = v.w;
        }
#pragma unroll
        for (int l = 0; l < 4; ++l) {
            int q = t + 256 * l;
            int kk = q >> 5, nn = (q & 31) << 2;
            *(float4*)&Bs[kk][nn] =
                *(const float4*)(g_w2t + (size_t)(kt + kk) * 128 + nn);
        }
        __syncthreads();
#pragma unroll
        for (int k = 0; k < 32; ++k) {
            double bd[4];
#pragma unroll
            for (int j = 0; j < 4; ++j)
                bd[j] = *(const double*)&Bs[k][tx * 8 + 2 * j];
            float a[10];
#pragma unroll
            for (int u = 0; u < 5; ++u) {
                float2 pv = *(const float2*)&As[k][ty * 10 + 2 * u];
                a[2 * u] = pv.x; a[2 * u + 1] = pv.y;
            }
#pragma unroll
            for (int i = 0; i < 10; ++i) {
                double a2 = pack2(a[i], a[i]);
#pragma unroll
                for (int j = 0; j < 4; ++j)
                    acc[i][j] = ffma2(a2, bd[j], acc[i][j]);
            }
        }
        __syncthreads();
    }

    /* epilogue: BN2+ReLU, softmax pool over the 20 rows of each point.
       thread ty covers rows ty*10..ty*10+9; partner = ty^1 (lane^16).   */
    const int ob = tx * 8;
    float res[8];
#pragma unroll
    for (int jd = 0; jd < 4; ++jd) {
        const int o0 = ob + 2 * jd, o1 = o0 + 1;
        const float mu0 = g_mu[64 + o0], rs0 = g_rs[64 + o0];
        const float mu1 = g_mu[64 + o1], rs1 = g_rs[64 + o1];
        const float gg0 = g2[o0], bb0 = b2v[o0];
        const float gg1 = g2[o1], bb1 = b2v[o1];
        float hm0 = 0.f, hm1 = 0.f;
#pragma unroll
        for (int i = 0; i < 10; ++i) {
            float2 c = unpack2(acc[i][jd]);
            float h0 = fmaxf(fmaf((c.x - mu0) * rs0, gg0, bb0), 0.f);
            float h1 = fmaxf(fmaf((c.y - mu1) * rs1, gg1, bb1), 0.f);
            hm0 = fmaxf(hm0, h0);
            hm1 = fmaxf(hm1, h1);
        }
        hm0 = fmaxf(hm0, __shfl_xor_sync(0xffffffffu, hm0, 16));
        hm1 = fmaxf(hm1, __shfl_xor_sync(0xffffffffu, hm1, 16));
        float se0 = 0.f, sw0 = 0.f, se1 = 0.f, sw1 = 0.f;
#pragma unroll
        for (int i = 0; i < 10; ++i) {
            float2 c = unpack2(acc[i][jd]);
            float h0 = fmaxf(fmaf((c.x - mu0) * rs0, gg0, bb0), 0.f);
            float h1 = fmaxf(fmaf((c.y - mu1) * rs1, gg1, bb1), 0.f);
            float e0 = __expf(h0 - hm0);
            float e1 = __expf(h1 - hm1);
            se0 += e0; sw0 = fmaf(e0, h0, sw0);
            se1 += e1; sw1 = fmaf(e1, h1, sw1);
        }
        se0 += __shfl_xor_sync(0xffffffffu, se0, 16);
        sw0 += __shfl_xor_sync(0xffffffffu, sw0, 16);
        se1 += __shfl_xor_sync(0xffffffffu, se1, 16);
        sw1 += __shfl_xor_sync(0xffffffffu, sw1, 16);
        res[2 * jd] = sw0 / se0;
        res[2 * jd + 1] = sw1 / se1;
    }
    if ((ty & 1) == 0) {
        const int p = mbase / KNB + (ty >> 1);
        float* cp = g_cat + (size_t)p * 192 + 64 + ob;
        *(float4*)cp       = make_float4(res[0], res[1], res[2], res[3]);
        *(float4*)(cp + 4) = make_float4(res[4], res[5], res[6], res[7]);
    }
}

/* ================= cat Gram (192x192) + colsum ======================= */
/* grid 128 x 256 rows; 256 thr, 12x12 micro tiles.                      */
__global__ __launch_bounds__(256) void catgram_kernel() {
    __shared__ float sm[16][196];
    const int t = threadIdx.x;
    const int i16 = t & 15, j16 = t >> 4;

    double acc[12][6];
#pragma unroll
    for (int i = 0; i < 12; ++i)
#pragma unroll
        for (int j = 0; j < 6; ++j) acc[i][j] = 0.0;
    float cs[12];
#pragma unroll
    for (int u = 0; u < 12; ++u) cs[u] = 0.f;

    for (int c = 0; c < 16; ++c) {
        const int rowbase = blockIdx.x * 256 + c * 16;
#pragma unroll
        for (int l = 0; l < 3; ++l) {
            int q = t + 256 * l;
            int r = q / 48, cq = (q % 48) * 4;
            *(float4*)&sm[r][cq] =
                *(const float4*)(g_cat + (size_t)(rowbase + r) * 192 + cq);
        }
        __syncthreads();
#pragma unroll 4
        for (int r = 0; r < 16; ++r) {
            float a[12];
#pragma unroll
            for (int u = 0; u < 6; ++u) {
                float2 pv = *(const float2*)&sm[r][i16 * 12 + 2 * u];
                a[2 * u] = pv.x; a[2 * u + 1] = pv.y;
            }
            double bd[6];
#pragma unroll
            for (int u = 0; u < 6; ++u)
                bd[u] = *(const double*)&sm[r][j16 * 12 + 2 * u];
#pragma unroll
            for (int i = 0; i < 12; ++i) {
                double a2 = pack2(a[i], a[i]);
#pragma unroll
                for (int j = 0; j < 6; ++j)
                    acc[i][j] = ffma2(a2, bd[j], acc[i][j]);
            }
            if (j16 == 0) {
#pragma unroll
                for (int u = 0; u < 12; ++u) cs[u] += a[u];
            }
        }
        __syncthreads();
    }
    float* cp = g_cpart + (size_t)blockIdx.x * 36864;
#pragma unroll
    for (int i = 0; i < 12; ++i) {
        float* row = cp + (i16 * 12 + i) * 192 + j16 * 12;
#pragma unroll
        for (int j = 0; j < 6; ++j) {
            float2 v = unpack2(acc[i][j]);
            *(float2*)(row + 2 * j) = v;
        }
    }
    if (j16 == 0) {
#pragma unroll
        for (int u = 0; u < 12; ++u)
            g_cspart[blockIdx.x * 192 + i16 * 12 + u] = cs[u];
    }
}

/* ================= reduce cat gram + colsum ========================== */
__global__ void gram3fin_kernel() {
    const int t = threadIdx.x;
    if (blockIdx.x == 144) {
        if (t < 192) {
            float a = 0.f;
            for (int p = 0; p < 128; ++p) a += g_cspart[p * 192 + t];
            g_catsum[t] = a;
        }
        return;
    }
    const int e = blockIdx.x * 256 + t;
    float a = 0.f;
    for (int p = 0; p < 128; ++p) a += g_cpart[(size_t)p * 36864 + e];
    g_cgram[e] = a;
}

/* ================= BN3 stats from cat Gram =========================== */
__global__ void bn3fin_kernel() {
    const int o = blockIdx.x;   /* 256 channels */
    const int i = threadIdx.x;  /* 192 */
    __shared__ float w[192], rq[192], rm[192];
    w[i] = g_w3t[i * 256 + o];
    __syncthreads();
    float qi = 0.f;
    const float* Gi = g_cgram + i * 192;
#pragma unroll 8
    for (int j = 0; j < 192; ++j) qi = fmaf(Gi[j], w[j], qi);
    rq[i] = qi * w[i];
    rm[i] = w[i] * g_catsum[i];
    __syncthreads();
    for (int s = 96; s >= 3; s >>= 1) {
        if (i < s) { rq[i] += rq[i + s]; rm[i] += rm[i + s]; }
        __syncthreads();
    }
    if (i == 0) {
        const float invN = 1.f / (float)NPTS;
        float mu = (rm[0] + rm[1] + rm[2]) * invN;
        float var = (rq[0] + rq[1] + rq[2]) * invN - mu * mu;
        g_mu[192 + o] = mu;
        g_rs[192 + o] = rsqrtf(var + EPSB);
    }
}

/* ================= GEMM3 + BN3 + ReLU + transposed write ============= */
/* 128x128 tiles, K=192; 256 thr, 8x8 micro, f32x2.                      */
__global__ __launch_bounds__(256) void gemm3out_kernel(
        const float* __restrict__ g3, const float* __restrict__ b3,
        float* __restrict__ out) {
    __shared__ float As[32][132];
    __shared__ float Bs[32][128];
    const int t = threadIdx.x;
    const int tx = t & 15, ty = t >> 4;
    const int mbase = blockIdx.x * 128;
    const int nbase = blockIdx.y * 128;

    double acc[8][4];
#pragma unroll
    for (int i = 0; i < 8; ++i)
#pragma unroll
        for (int j = 0; j < 4; ++j) acc[i][j] = 0.0;

    for (int kt = 0; kt < 192; kt += 32) {
#pragma unroll
        for (int l = 0; l < 4; ++l) {
            int q = t + 256 * l;
            int r = q >> 3, kq = (q & 7) << 2;
            float4 v = *(const float4*)(g_cat + (size_t)(mbase + r) * 192 + kt + kq);
            As[kq + 0][r] = v.x;
            As[kq + 1][r] = v.y;
            As[kq + 2][r] = v.z;
            As[kq + 3][r] = v.w;
        }
#pragma unroll
        for (int l = 0; l < 4; ++l) {
            int q = t + 256 * l;
            int kk = q >> 5, nn = (q & 31) << 2;
            *(float4*)&Bs[kk][nn] =
                *(const float4*)(g_w3t + (size_t)(kt + kk) * 256 + nbase + nn);
        }
        __syncthreads();
#pragma unroll
        for (int k = 0; k < 32; ++k) {
            double bd[4];
#pragma unroll
            for (int j = 0; j < 4; ++j)
                bd[j] = *(const double*)&Bs[k][tx * 8 + 2 * j];
            float4 a0 = *(const float4*)&As[k][ty * 8];
            float4 a1 = *(const float4*)&As[k][ty * 8 + 4];
            const float av[8] = {a0.x, a0.y, a0.z, a0.w, a1.x, a1.y, a1.z, a1.w};
#pragma unroll
            for (int i = 0; i < 8; ++i) {
                double a2 = pack2(av[i], av[i]);
#pragma unroll
                for (int j = 0; j < 4; ++j)
                    acc[i][j] = ffma2(a2, bd[j], acc[i][j]);
            }
        }
        __syncthreads();
    }

    /* epilogue: BN3+ReLU, write out[b, o, n] (transposed, coalesced n) */
    const int n0 = mbase + ty * 8;
    const int b = n0 >> 12;
    const int n = n0 & (NN - 1);
#pragma unroll
    for (int jd = 0; jd < 4; ++jd) {
        float2 c[8];
#pragma unroll
        for (int i = 0; i < 8; ++i) c[i] = unpack2(acc[i][jd]);
#pragma unroll
        for (int half = 0; half < 2; ++half) {
            const int o = nbase + tx * 8 + 2 * jd + half;
            const float mu = g_mu[192 + o], rs = g_rs[192 + o];
            const float gg = g3[o], bb = b3[o];
            float v[8];
#pragma unroll
            for (int i = 0; i < 8; ++i) {
                float y = half ? c[i].y : c[i].x;
                v[i] = fmaxf(fmaf((y - mu) * rs, gg, bb), 0.f);
            }
            float* op = out + ((size_t)b * 256 + o) * NN + n;
            *(float4*)op       = make_float4(v[0], v[1], v[2], v[3]);
            *(float4*)(op + 4) = make_float4(v[4], v[5], v[6], v[7]);
        }
    }
}

/* ================= launcher ========================================== */
extern "C" void kernel_launch(void* const* d_in, const int* in_sizes, int n_in,
                              void* d_out, int out_size) {
    const float* x  = (const float*)d_in[0];
    const float* W1 = (const float*)d_in[1];
    const float* g1 = (const float*)d_in[2];
    const float* b1 = (const float*)d_in[3];
    const float* W2 = (const float*)d_in[4];
    const float* g2 = (const float*)d_in[5];
    const float* b2 = (const float*)d_in[6];
    const float* W3 = (const float*)d_in[7];
    const float* g3 = (const float*)d_in[8];
    const float* b3 = (const float*)d_in[9];
    float* out = (float*)d_out;

    prep_kernel<<<192, 256>>>(W2, W3);
    knn_kernel<<<dim3(BB, NN / 256), 256>>>(x);

    fgram_kernel<<<640, 256>>>(x);
    bn1fin_kernel<<<1, 256>>>(W1);

    h1pool_kernel<<<NPTS / 4, 256>>>(x, W1, g1, b1);

    h1gram_kernel<<<640, 256>>>();
    gram2fin_kernel<<<65, 256>>>();
    bn2fin_kernel<<<128, 64>>>();

    gemm2pool_kernel<<<M1 / 160, 256>>>(g2, b2);

    catgram_kernel<<<128, 256>>>();
    gram3fin_kernel<<<145, 256>>>();
    bn3fin_kernel<<<256, 192>>>();

    gemm3out_kernel<<<dim3(NPTS / 128, 2), 256>>>(g3, b3, out);

    (void)in_sizes; (void)n_in; (void)out_size;
}

// round 6
// speedup vs baseline: 1.8106x; 1.8106x over previous
#include <cuda_runtime.h>
#include <cstdint>

#define BB    8
#define NN    4096
#define KNB   20
#define NPTS  (BB * NN)          /* 32768  */
#define M1    (NPTS * KNB)       /* 655360 */
#define EPSB  1e-5f

/* ================= static device scratch (no allocations) ============= */
__device__ int   g_idx[M1];                         /* knn indices          */
__device__ float g_cat[(size_t)NPTS * 192];         /* [x1|x2] [P,192]      */
__device__ float g_w2t[64 * 128];                   /* W2^T [k][o]          */
__device__ float g_w3t[192 * 256];                  /* W3^T [k][o]          */
__device__ float g_fpart[640 * 27];                 /* feat gram partials   */
__device__ float g_colpart[64 * 8192];              /* h1 colsum partials   */
__device__ float g_gpart[(size_t)640 * 4096];       /* h1 gram partials     */
__device__ float g_gram[4096];                      /* h1 gram 64x64        */
__device__ float g_h1colsum[64];
__device__ float g_cpart[(size_t)128 * 36864];      /* cat gram partials    */
__device__ float g_cspart[128 * 192];               /* cat colsum partials  */
__device__ float g_cgram[36864];                    /* cat gram 192x192     */
__device__ float g_catsum[192];
__device__ float g_mu[448];                         /* L1:0 L2:64 L3:192    */
__device__ float g_rs[448];

/* ================= f32x2 packed-math helpers ========================= */
__device__ __forceinline__ double pack2(float x, float y) {
    double d;
    asm("mov.b64 %0, {%1, %2};" : "=d"(d) : "f"(x), "f"(y));
    return d;
}
__device__ __forceinline__ float2 unpack2(double d) {
    float2 r;
    asm("mov.b64 {%0, %1}, %2;" : "=f"(r.x), "=f"(r.y) : "d"(d));
    return r;
}
__device__ __forceinline__ double ffma2(double a, double b, double c) {
    double d;
    asm("fma.rn.f32x2 %0, %1, %2, %3;" : "=d"(d) : "d"(a), "d"(b), "d"(c));
    return d;
}

/* ================= prep: transpose W2, W3 ============================ */
__global__ void prep_kernel(const float* __restrict__ W2,
                            const float* __restrict__ W3) {
    int t = blockIdx.x * blockDim.x + threadIdx.x;
    if (t < 64 * 128) {
        int k = t / 128, o = t % 128;
        g_w2t[t] = W2[o * 64 + k];
    }
    if (t < 192 * 256) {
        int k = t / 256, o = t % 256;
        g_w3t[t] = W3[o * 192 + k];
    }
}

/* ================= kNN: branch-light buffered top-20 ================= */
/* key v = 2 q.m - |m|^2  (order-equivalent to -||q-m||^2).              */
/* Top-20 kept SORTED in statically-indexed registers (SEL chains only). */
/* Hot loop: compare vs threshold, rare append to write-only local buf.  */
/* Every 32 candidates: if any lane's buffer is filling, all lanes       */
/* batch-insert their buffered items in parallel.                        */
#define KTILE 512
#define BUFSZ 64

__device__ __forceinline__ void ins20(float v, int id, float* s, int* si) {
    bool c[20];
#pragma unroll
    for (int t = 0; t < 20; ++t) c[t] = v > s[t];
#pragma unroll
    for (int t = 19; t >= 1; --t) {
        float nv = c[t - 1] ? s[t - 1] : v;
        int   ni = c[t - 1] ? si[t - 1] : id;
        s[t]  = c[t] ? nv : s[t];
        si[t] = c[t] ? ni : si[t];
    }
    s[0]  = c[0] ? v : s[0];
    si[0] = c[0] ? id : si[0];
}

__global__ void knn_kernel(const float* __restrict__ x) {
    __shared__ float4 pts[KTILE];
    const int b = blockIdx.x;
    const int n = blockIdx.y * blockDim.x + threadIdx.x;
    const float* xb = x + b * 3 * NN;
    const float qx = xb[n], qy = xb[NN + n], qz = xb[2 * NN + n];
    const float q2x = 2.f * qx, q2y = 2.f * qy, q2z = 2.f * qz;

    float s[20];
    int   si[20];
#pragma unroll
    for (int t = 0; t < 20; ++t) { s[t] = -3.0e38f; si[t] = 0; }
    float thr = -3.0e38f;

    float bufv[BUFSZ];
    int   bufi[BUFSZ];
    int   cnt = 0;

    for (int base = 0; base < NN; base += KTILE) {
        __syncthreads();
        for (int m = threadIdx.x; m < KTILE; m += blockDim.x) {
            float px = xb[base + m], py = xb[NN + base + m], pz = xb[2 * NN + base + m];
            pts[m] = make_float4(px, py, pz, fmaf(px, px, fmaf(py, py, pz * pz)));
        }
        __syncthreads();

        for (int g = 0; g < KTILE; g += 32) {
#pragma unroll
            for (int j = 0; j < 32; ++j) {
                float4 p = pts[g + j];
                float v = fmaf(q2x, p.x, fmaf(q2y, p.y, fmaf(q2z, p.z, -p.w)));
                if (v > thr) { bufv[cnt] = v; bufi[cnt] = base + g + j; ++cnt; }
            }
            if (__any_sync(0xffffffffu, cnt >= 32)) {
                int mx = cnt;
#pragma unroll
                for (int o = 16; o; o >>= 1)
                    mx = max(mx, __shfl_xor_sync(0xffffffffu, mx, o));
                for (int q = 0; q < mx; ++q) {
                    float v = (q < cnt) ? bufv[q] : -3.2e38f;
                    int   i = (q < cnt) ? bufi[q] : 0;
                    ins20(v, i, s, si);
                }
                cnt = 0;
                thr = s[19];
            }
        }
    }
    /* final flush */
    {
        int mx = cnt;
#pragma unroll
        for (int o = 16; o; o >>= 1)
            mx = max(mx, __shfl_xor_sync(0xffffffffu, mx, o));
        for (int q = 0; q < mx; ++q) {
            float v = (q < cnt) ? bufv[q] : -3.2e38f;
            int   i = (q < cnt) ? bufi[q] : 0;
            ins20(v, i, s, si);
        }
    }
    int* op = g_idx + (size_t)(b * NN + n) * KNB;
#pragma unroll
    for (int t = 0; t < 20; ++t) op[t] = si[t];
}

/* ================= feat Gram (6x6 sym = 21) + feat colsum (6) ======== */
__global__ void fgram_kernel(const float* __restrict__ x) {
    const int t = threadIdx.x;
    float s[27];
#pragma unroll
    for (int v = 0; v < 27; ++v) s[v] = 0.f;

    for (int e = 0; e < 4; ++e) {
        int m = blockIdx.x * 1024 + e * 256 + t;
        int p = m / KNB;
        int b = p >> 12, n = p & (NN - 1);
        const float* xb = x + b * 3 * NN;
        int nb = g_idx[m];
        float cx = xb[n], cy = xb[NN + n], cz = xb[2 * NN + n];
        float f[6];
        f[0] = xb[nb] - cx;
        f[1] = xb[NN + nb] - cy;
        f[2] = xb[2 * NN + nb] - cz;
        f[3] = cx; f[4] = cy; f[5] = cz;
        int u = 0;
#pragma unroll
        for (int i = 0; i < 6; ++i) {
            s[21 + i] += f[i];
#pragma unroll
            for (int j = 0; j <= i; ++j) s[u++] = fmaf(f[i], f[j], s[u]);
        }
    }
#pragma unroll
    for (int off = 16; off; off >>= 1)
#pragma unroll
        for (int v = 0; v < 27; ++v)
            s[v] += __shfl_xor_sync(0xffffffffu, s[v], off);

    __shared__ float sm[8][27];
    if ((t & 31) == 0)
#pragma unroll
        for (int v = 0; v < 27; ++v) sm[t >> 5][v] = s[v];
    __syncthreads();
    if (t < 27) {
        float a = 0.f;
#pragma unroll
        for (int w = 0; w < 8; ++w) a += sm[w][t];
        g_fpart[blockIdx.x * 27 + t] = a;
    }
}

/* ================= BN1 stats from feat Gram ========================== */
__global__ void bn1fin_kernel(const float* __restrict__ W1) {
    __shared__ float part[27][8];
    __shared__ float gf[27];
    const int t = threadIdx.x;
    if (t < 216) {
        int j = t / 8, sl = t % 8;
        float a = 0.f;
        for (int i = sl; i < 640; i += 8) a += g_fpart[i * 27 + j];
        part[j][sl] = a;
    }
    __syncthreads();
    if (t < 27) {
        float a = 0.f;
#pragma unroll
        for (int sl = 0; sl < 8; ++sl) a += part[t][sl];
        gf[t] = a;
    }
    __syncthreads();
    if (t < 64) {
        float w[6];
#pragma unroll
        for (int c = 0; c < 6; ++c) w[c] = W1[t * 6 + c];
        const float invM = 1.f / (float)M1;
        float mu = 0.f;
#pragma unroll
        for (int i = 0; i < 6; ++i) mu = fmaf(w[i], gf[21 + i], mu);
        mu *= invM;
        float q = 0.f;
#pragma unroll
        for (int i = 0; i < 6; ++i)
#pragma unroll
            for (int j = 0; j <= i; ++j) {
                float val = gf[i * (i + 1) / 2 + j];
                float c = w[i] * w[j] * val;
                q += (i == j) ? c : 2.f * c;
            }
        q *= invM;
        g_mu[t] = mu;
        g_rs[t] = rsqrtf(q - mu * mu + EPSB);
    }
}

/* ================= h1 pool -> x1 (+ h1 colsum partials) ============== */
/* h1 recomputed on the fly; never stored to gmem.                       */
__global__ void h1pool_kernel(const float* __restrict__ x,
                              const float* __restrict__ W1,
                              const float* __restrict__ g1,
                              const float* __restrict__ b1) {
    __shared__ float feat[80][6];
    __shared__ float red[4][64];
    const int t  = threadIdx.x;
    const int o  = t & 63;
    const int pl = t >> 6;

    if (t < 80) {
        int p = blockIdx.x * 4 + t / 20;
        int k = t % 20;
        int m = p * KNB + k;
        int b = p >> 12, n = p & (NN - 1);
        const float* xb = x + b * 3 * NN;
        int nb = g_idx[m];
        float cx = xb[n], cy = xb[NN + n], cz = xb[2 * NN + n];
        feat[t][0] = xb[nb] - cx;
        feat[t][1] = xb[NN + nb] - cy;
        feat[t][2] = xb[2 * NN + nb] - cz;
        feat[t][3] = cx; feat[t][4] = cy; feat[t][5] = cz;
    }
    __syncthreads();

    float wr[6];
#pragma unroll
    for (int c = 0; c < 6; ++c) wr[c] = W1[o * 6 + c];
    const float mu = g_mu[o], rs = g_rs[o], gg = g1[o], bb = b1[o];

    const int p = blockIdx.x * 4 + pl;

    float h[KNB];
    float hmax = 0.f, cs = 0.f;
#pragma unroll
    for (int k = 0; k < KNB; ++k) {
        const float* f = feat[pl * KNB + k];
        float y = wr[0] * f[0];
        y = fmaf(wr[1], f[1], y);
        y = fmaf(wr[2], f[2], y);
        y = fmaf(wr[3], f[3], y);
        y = fmaf(wr[4], f[4], y);
        y = fmaf(wr[5], f[5], y);
        float hv = fmaxf(fmaf((y - mu) * rs, gg, bb), 0.f);
        h[k] = hv;
        hmax = fmaxf(hmax, hv);
        cs += hv;
    }
    float se = 0.f, sw = 0.f;
#pragma unroll
    for (int k = 0; k < KNB; ++k) {
        float e = __expf(h[k] - hmax);
        se += e;
        sw = fmaf(e, h[k], sw);
    }
    g_cat[(size_t)p * 192 + o] = sw / se;

    red[pl][o] = cs;
    __syncthreads();
    if (pl == 0)
        g_colpart[(size_t)o * 8192 + blockIdx.x] =
            red[0][o] + red[1][o] + red[2][o] + red[3][o];
}

/* ================= h1 Gram (64x64) partials, h1 recomputed =========== */
/* grid 640 x 1024 rows, chunks of 32, double-buffered feat gather.      */
__global__ __launch_bounds__(256) void h1gram_kernel(
        const float* __restrict__ x,  const float* __restrict__ W1,
        const float* __restrict__ g1, const float* __restrict__ b1) {
    __shared__ float hs[32][68];
    __shared__ float f6[2][32][8];
    const int t = threadIdx.x;
    const int i16 = t & 15, j16 = t >> 4;
    const int c  = t & 63;
    const int rg = t >> 6;

    float wr[6];
#pragma unroll
    for (int j = 0; j < 6; ++j) wr[j] = W1[c * 6 + j];
    const float mu = g_mu[c], rsv = g_rs[c], gg = g1[c], bb = b1[c];

    double acc[4][2];
#pragma unroll
    for (int i = 0; i < 4; ++i) { acc[i][0] = 0.0; acc[i][1] = 0.0; }

    /* prime gather for chunk 0 */
    if (t < 32) {
        int m = blockIdx.x * 1024 + t;
        int p = m / KNB, b_ = p >> 12, n_ = p & (NN - 1);
        const float* xb = x + b_ * 3 * NN;
        int nb = g_idx[m];
        float cx = xb[n_], cy = xb[NN + n_], cz = xb[2 * NN + n_];
        f6[0][t][0] = xb[nb] - cx;
        f6[0][t][1] = xb[NN + nb] - cy;
        f6[0][t][2] = xb[2 * NN + nb] - cz;
        f6[0][t][3] = cx; f6[0][t][4] = cy; f6[0][t][5] = cz;
    }

    for (int cc = 0; cc < 32; ++cc) {
        const int cur = cc & 1;
        __syncthreads();  /* f6[cur] ready; hs free (prev gram done) */

        /* prefetch next chunk's feat into the other buffer */
        if (cc + 1 < 32 && t < 32) {
            int m = blockIdx.x * 1024 + (cc + 1) * 32 + t;
            int p = m / KNB, b_ = p >> 12, n_ = p & (NN - 1);
            const float* xb = x + b_ * 3 * NN;
            int nb = g_idx[m];
            float cx = xb[n_], cy = xb[NN + n_], cz = xb[2 * NN + n_];
            f6[cur ^ 1][t][0] = xb[nb] - cx;
            f6[cur ^ 1][t][1] = xb[NN + nb] - cy;
            f6[cur ^ 1][t][2] = xb[2 * NN + nb] - cz;
            f6[cur ^ 1][t][3] = cx; f6[cur ^ 1][t][4] = cy; f6[cur ^ 1][t][5] = cz;
        }

        /* fill hs[32][64]: thread (c, rg) does rows rg, rg+4, ... */
#pragma unroll
        for (int rr = 0; rr < 8; ++rr) {
            const int r = rg + rr * 4;
            const float* f = f6[cur][r];
            float y = wr[0] * f[0];
            y = fmaf(wr[1], f[1], y);
            y = fmaf(wr[2], f[2], y);
            y = fmaf(wr[3], f[3], y);
            y = fmaf(wr[4], f[4], y);
            y = fmaf(wr[5], f[5], y);
            hs[r][c] = fmaxf(fmaf((y - mu) * rsv, gg, bb), 0.f);
        }
        __syncthreads();  /* hs ready */

#pragma unroll 8
        for (int r = 0; r < 32; ++r) {
            float4 a = *(const float4*)&hs[r][i16 * 4];
            double b0 = *(const double*)&hs[r][j16 * 4];
            double b1d = *(const double*)&hs[r][j16 * 4 + 2];
            const float av[4] = {a.x, a.y, a.z, a.w};
#pragma unroll
            for (int i = 0; i < 4; ++i) {
                double a2 = pack2(av[i], av[i]);
                acc[i][0] = ffma2(a2, b0, acc[i][0]);
                acc[i][1] = ffma2(a2, b1d, acc[i][1]);
            }
        }
    }
    float* gp = g_gpart + (size_t)blockIdx.x * 4096;
#pragma unroll
    for (int i = 0; i < 4; ++i) {
        float2 c0 = unpack2(acc[i][0]);
        float2 c1 = unpack2(acc[i][1]);
        float4 v = make_float4(c0.x, c0.y, c1.x, c1.y);
        *(float4*)(gp + (i16 * 4 + i) * 64 + j16 * 4) = v;
    }
}

/* ================= reduce h1 gram + colsum =========================== */
__global__ void gram2fin_kernel() {
    __shared__ float red[64][4];
    const int t = threadIdx.x;
    const int e = t >> 2, sl = t & 3;
    if (blockIdx.x == 64) {
        float a = 0.f;
        for (int i = sl; i < 8192; i += 4) a += g_colpart[(size_t)e * 8192 + i];
        red[e][sl] = a;
        __syncthreads();
        if (sl == 0)
            g_h1colsum[e] = red[e][0] + red[e][1] + red[e][2] + red[e][3];
        return;
    }
    const int ge = blockIdx.x * 64 + e;
    float a = 0.f;
    for (int i = sl; i < 640; i += 4) a += g_gpart[(size_t)i * 4096 + ge];
    red[e][sl] = a;
    __syncthreads();
    if (sl == 0)
        g_gram[ge] = red[e][0] + red[e][1] + red[e][2] + red[e][3];
}

/* ================= BN2 stats from h1 Gram ============================ */
__global__ void bn2fin_kernel() {
    const int o = blockIdx.x;
    const int i = threadIdx.x;
    __shared__ float w[64], rq[64], rm[64];
    w[i] = g_w2t[i * 128 + o];
    __syncthreads();
    float qi = 0.f;
    const float* Gi = g_gram + i * 64;
#pragma unroll 8
    for (int j = 0; j < 64; ++j) qi = fmaf(Gi[j], w[j], qi);
    rq[i] = qi * w[i];
    rm[i] = w[i] * g_h1colsum[i];
    __syncthreads();
    for (int s = 32; s > 0; s >>= 1) {
        if (i < s) { rq[i] += rq[i + s]; rm[i] += rm[i + s]; }
        __syncthreads();
    }
    if (i == 0) {
        const float invM = 1.f / (float)M1;
        float mu = rm[0] * invM;
        float var = rq[0] * invM - mu * mu;
        g_mu[64 + o] = mu;
        g_rs[64 + o] = rsqrtf(var + EPSB);
    }
}

/* ================= GEMM2 (h1 on the fly) + BN2 + ReLU + pool ========= */
/* 160x128 tiles (8 points x 20 nbrs); conflict-free lane mapping:       */
/* rows ty*10+i, cols 2*tx + 32*jd (f32x2 pairs).                        */
__global__ __launch_bounds__(256) void gemm2pool_kernel(
        const float* __restrict__ x,  const float* __restrict__ W1,
        const float* __restrict__ g1, const float* __restrict__ b1,
        const float* __restrict__ g2, const float* __restrict__ b2v) {
    __shared__ float f6[160][8];
    __shared__ float As[64][166];   /* [chan][row], pad 166: 8B-aligned rows */
    __shared__ float Bs[64][128];
    const int t = threadIdx.x;
    const int tx = t & 15, ty = t >> 4;
    const int mbase = blockIdx.x * 160;

    /* gather feat rows */
    if (t < 160) {
        int m = mbase + t;
        int p = m / KNB, b_ = p >> 12, n_ = p & (NN - 1);
        const float* xb = x + b_ * 3 * NN;
        int nb = g_idx[m];
        float cx = xb[n_], cy = xb[NN + n_], cz = xb[2 * NN + n_];
        f6[t][0] = xb[nb] - cx;
        f6[t][1] = xb[NN + nb] - cy;
        f6[t][2] = xb[2 * NN + nb] - cz;
        f6[t][3] = cx; f6[t][4] = cy; f6[t][5] = cz;
    }
    /* load Bs = W2^T (64x128) */
#pragma unroll
    for (int l = 0; l < 8; ++l) {
        int q = t + 256 * l;
        int kk = q >> 5, nn = (q & 31) << 2;
        *(float4*)&Bs[kk][nn] = *(const float4*)(g_w2t + kk * 128 + nn);
    }
    __syncthreads();

    /* fill As[c][r] = h1 value (recomputed) */
    {
        const int c  = t & 63;
        const int rg = t >> 6;
        float wr[6];
#pragma unroll
        for (int j = 0; j < 6; ++j) wr[j] = W1[c * 6 + j];
        const float mu = g_mu[c], rsv = g_rs[c], gg = g1[c], bb = b1[c];
#pragma unroll 4
        for (int rr = 0; rr < 40; ++rr) {
            const int r = rg + rr * 4;
            const float* f = f6[r];
            float y = wr[0] * f[0];
            y = fmaf(wr[1], f[1], y);
            y = fmaf(wr[2], f[2], y);
            y = fmaf(wr[3], f[3], y);
            y = fmaf(wr[4], f[4], y);
            y = fmaf(wr[5], f[5], y);
            As[c][r] = fmaxf(fmaf((y - mu) * rsv, gg, bb), 0.f);
        }
    }
    __syncthreads();

    double acc[10][4];
#pragma unroll
    for (int i = 0; i < 10; ++i)
#pragma unroll
        for (int j = 0; j < 4; ++j) acc[i][j] = 0.0;

#pragma unroll 4
    for (int k = 0; k < 64; ++k) {
        double bd[4];
#pragma unroll
        for (int jd = 0; jd < 4; ++jd)
            bd[jd] = *(const double*)&Bs[k][2 * tx + 32 * jd];
        float a[10];
#pragma unroll
        for (int u = 0; u < 5; ++u) {
            float2 pv = *(const float2*)&As[k][ty * 10 + 2 * u];
            a[2 * u] = pv.x; a[2 * u + 1] = pv.y;
        }
#pragma unroll
        for (int i = 0; i < 10; ++i) {
            double a2 = pack2(a[i], a[i]);
#pragma unroll
            for (int jd = 0; jd < 4; ++jd)
                acc[i][jd] = ffma2(a2, bd[jd], acc[i][jd]);
        }
    }

    /* epilogue: BN2+ReLU, softmax-pool over 20 rows (partner lane ^16) */
    float resv[8];
#pragma unroll
    for (int jd = 0; jd < 4; ++jd) {
        const int o0 = 32 * jd + 2 * tx, o1 = o0 + 1;
        const float mu0 = g_mu[64 + o0], rs0 = g_rs[64 + o0];
        const float mu1 = g_mu[64 + o1], rs1 = g_rs[64 + o1];
        const float gg0 = g2[o0], bb0 = b2v[o0];
        const float gg1 = g2[o1], bb1 = b2v[o1];
        float hm0 = 0.f, hm1 = 0.f;
#pragma unroll
        for (int i = 0; i < 10; ++i) {
            float2 c = unpack2(acc[i][jd]);
            float h0 = fmaxf(fmaf((c.x - mu0) * rs0, gg0, bb0), 0.f);
            float h1 = fmaxf(fmaf((c.y - mu1) * rs1, gg1, bb1), 0.f);
            hm0 = fmaxf(hm0, h0);
            hm1 = fmaxf(hm1, h1);
        }
        hm0 = fmaxf(hm0, __shfl_xor_sync(0xffffffffu, hm0, 16));
        hm1 = fmaxf(hm1, __shfl_xor_sync(0xffffffffu, hm1, 16));
        float se0 = 0.f, sw0 = 0.f, se1 = 0.f, sw1 = 0.f;
#pragma unroll
        for (int i = 0; i < 10; ++i) {
            float2 c = unpack2(acc[i][jd]);
            float h0 = fmaxf(fmaf((c.x - mu0) * rs0, gg0, bb0), 0.f);
            float h1 = fmaxf(fmaf((c.y - mu1) * rs1, gg1, bb1), 0.f);
            float e0 = __expf(h0 - hm0);
            float e1 = __expf(h1 - hm1);
            se0 += e0; sw0 = fmaf(e0, h0, sw0);
            se1 += e1; sw1 = fmaf(e1, h1, sw1);
        }
        se0 += __shfl_xor_sync(0xffffffffu, se0, 16);
        sw0 += __shfl_xor_sync(0xffffffffu, sw0, 16);
        se1 += __shfl_xor_sync(0xffffffffu, se1, 16);
        sw1 += __shfl_xor_sync(0xffffffffu, sw1, 16);
        resv[2 * jd]     = sw0 / se0;
        resv[2 * jd + 1] = sw1 / se1;
    }
    if ((ty & 1) == 0) {
        const int p = mbase / KNB + (ty >> 1);
#pragma unroll
        for (int jd = 0; jd < 4; ++jd)
            *(float2*)&g_cat[(size_t)p * 192 + 64 + 32 * jd + 2 * tx] =
                make_float2(resv[2 * jd], resv[2 * jd + 1]);
    }
}

/* ================= cat Gram (192x192) + colsum ======================= */
__global__ __launch_bounds__(256) void catgram_kernel() {
    __shared__ float sm[16][196];
    const int t = threadIdx.x;
    const int i16 = t & 15, j16 = t >> 4;

    double acc[12][6];
#pragma unroll
    for (int i = 0; i < 12; ++i)
#pragma unroll
        for (int j = 0; j < 6; ++j) acc[i][j] = 0.0;
    float cs[12];
#pragma unroll
    for (int u = 0; u < 12; ++u) cs[u] = 0.f;

    for (int c = 0; c < 16; ++c) {
        const int rowbase = blockIdx.x * 256 + c * 16;
#pragma unroll
        for (int l = 0; l < 3; ++l) {
            int q = t + 256 * l;
            int r = q / 48, cq = (q % 48) * 4;
            *(float4*)&sm[r][cq] =
                *(const float4*)(g_cat + (size_t)(rowbase + r) * 192 + cq);
        }
        __syncthreads();
#pragma unroll 4
        for (int r = 0; r < 16; ++r) {
            float a[12];
#pragma unroll
            for (int u = 0; u < 6; ++u) {
                float2 pv = *(const float2*)&sm[r][i16 * 12 + 2 * u];
                a[2 * u] = pv.x; a[2 * u + 1] = pv.y;
            }
            double bd[6];
#pragma unroll
            for (int u = 0; u < 6; ++u)
                bd[u] = *(const double*)&sm[r][j16 * 12 + 2 * u];
#pragma unroll
            for (int i = 0; i < 12; ++i) {
                double a2 = pack2(a[i], a[i]);
#pragma unroll
                for (int j = 0; j < 6; ++j)
                    acc[i][j] = ffma2(a2, bd[j], acc[i][j]);
            }
            if (j16 == 0) {
#pragma unroll
                for (int u = 0; u < 12; ++u) cs[u] += a[u];
            }
        }
        __syncthreads();
    }
    float* cp = g_cpart + (size_t)blockIdx.x * 36864;
#pragma unroll
    for (int i = 0; i < 12; ++i) {
        float* row = cp + (i16 * 12 + i) * 192 + j16 * 12;
#pragma unroll
        for (int j = 0; j < 6; ++j) {
            float2 v = unpack2(acc[i][j]);
            *(float2*)(row + 2 * j) = v;
        }
    }
    if (j16 == 0) {
#pragma unroll
        for (int u = 0; u < 12; ++u)
            g_cspart[blockIdx.x * 192 + i16 * 12 + u] = cs[u];
    }
}

/* ================= reduce cat gram + colsum ========================== */
__global__ void gram3fin_kernel() {
    const int t = threadIdx.x;
    if (blockIdx.x == 144) {
        if (t < 192) {
            float a = 0.f;
            for (int p = 0; p < 128; ++p) a += g_cspart[p * 192 + t];
            g_catsum[t] = a;
        }
        return;
    }
    const int e = blockIdx.x * 256 + t;
    float a = 0.f;
    for (int p = 0; p < 128; ++p) a += g_cpart[(size_t)p * 36864 + e];
    g_cgram[e] = a;
}

/* ================= BN3 stats from cat Gram =========================== */
__global__ void bn3fin_kernel() {
    const int o = blockIdx.x;
    const int i = threadIdx.x;
    __shared__ float w[192], rq[192], rm[192];
    w[i] = g_w3t[i * 256 + o];
    __syncthreads();
    float qi = 0.f;
    const float* Gi = g_cgram + i * 192;
#pragma unroll 8
    for (int j = 0; j < 192; ++j) qi = fmaf(Gi[j], w[j], qi);
    rq[i] = qi * w[i];
    rm[i] = w[i] * g_catsum[i];
    __syncthreads();
    for (int s = 96; s >= 3; s >>= 1) {
        if (i < s) { rq[i] += rq[i + s]; rm[i] += rm[i + s]; }
        __syncthreads();
    }
    if (i == 0) {
        const float invN = 1.f / (float)NPTS;
        float mu = (rm[0] + rm[1] + rm[2]) * invN;
        float var = (rq[0] + rq[1] + rq[2]) * invN - mu * mu;
        g_mu[192 + o] = mu;
        g_rs[192 + o] = rsqrtf(var + EPSB);
    }
}

/* ================= GEMM3 + BN3 + ReLU + transposed write ============= */
/* 128x128 tiles, K=192; conflict-free: rows 2*ty+32*u(+1),              */
/* cols 2*tx+32*jd (f32x2 pairs).                                        */
__global__ __launch_bounds__(256) void gemm3out_kernel(
        const float* __restrict__ g3, const float* __restrict__ b3,
        float* __restrict__ out) {
    __shared__ float As[32][134];
    __shared__ float Bs[32][128];
    const int t = threadIdx.x;
    const int tx = t & 15, ty = t >> 4;
    const int mbase = blockIdx.x * 128;
    const int nbase = blockIdx.y * 128;

    double acc[8][4];
#pragma unroll
    for (int i = 0; i < 8; ++i)
#pragma unroll
        for (int j = 0; j < 4; ++j) acc[i][j] = 0.0;

    for (int kt = 0; kt < 192; kt += 32) {
#pragma unroll
        for (int l = 0; l < 4; ++l) {
            int q = t + 256 * l;
            int r = q >> 3, kq = (q & 7) << 2;
            float4 v = *(const float4*)(g_cat + (size_t)(mbase + r) * 192 + kt + kq);
            As[kq + 0][r] = v.x;
            As[kq + 1][r] = v.y;
            As[kq + 2][r] = v.z;
            As[kq + 3][r] = v.w;
        }
#pragma unroll
        for (int l = 0; l < 4; ++l) {
            int q = t + 256 * l;
            int kk = q >> 5, nn = (q & 31) << 2;
            *(float4*)&Bs[kk][nn] =
                *(const float4*)(g_w3t + (size_t)(kt + kk) * 256 + nbase + nn);
        }
        __syncthreads();
#pragma unroll 4
        for (int k = 0; k < 32; ++k) {
            double bd[4];
#pragma unroll
            for (int jd = 0; jd < 4; ++jd)
                bd[jd] = *(const double*)&Bs[k][2 * tx + 32 * jd];
            float a[8];
#pragma unroll
            for (int u = 0; u < 4; ++u) {
                float2 pv = *(const float2*)&As[k][2 * ty + 32 * u];
                a[2 * u] = pv.x; a[2 * u + 1] = pv.y;
            }
#pragma unroll
            for (int i = 0; i < 8; ++i) {
                double a2 = pack2(a[i], a[i]);
#pragma unroll
                for (int jd = 0; jd < 4; ++jd)
                    acc[i][jd] = ffma2(a2, bd[jd], acc[i][jd]);
            }
        }
        __syncthreads();
    }

    /* epilogue: BN3 + ReLU, transposed coalesced-ish writes */
    const int b = mbase >> 12;
    const int nloc = mbase & (NN - 1);
#pragma unroll
    for (int jd = 0; jd < 4; ++jd) {
#pragma unroll
        for (int half = 0; half < 2; ++half) {
            const int o = nbase + 32 * jd + 2 * tx + half;
            const float mu = g_mu[192 + o], rsv = g_rs[192 + o];
            const float gg = g3[o], bb = b3[o];
#pragma unroll
            for (int u = 0; u < 4; ++u) {
                float2 clo = unpack2(acc[2 * u][jd]);
                float2 chi = unpack2(acc[2 * u + 1][jd]);
                float y0 = half ? clo.y : clo.x;
                float y1 = half ? chi.y : chi.x;
                float v0 = fmaxf(fmaf((y0 - mu) * rsv, gg, bb), 0.f);
                float v1 = fmaxf(fmaf((y1 - mu) * rsv, gg, bb), 0.f);
                float* op = out + ((size_t)b * 256 + o) * NN
                                + nloc + 2 * ty + 32 * u;
                *(float2*)op = make_float2(v0, v1);
            }
        }
    }
}

/* ================= launcher ========================================== */
extern "C" void kernel_launch(void* const* d_in, const int* in_sizes, int n_in,
                              void* d_out, int out_size) {
    const float* x  = (const float*)d_in[0];
    const float* W1 = (const float*)d_in[1];
    const float* g1 = (const float*)d_in[2];
    const float* b1 = (const float*)d_in[3];
    const float* W2 = (const float*)d_in[4];
    const float* g2 = (const float*)d_in[5];
    const float* b2 = (const float*)d_in[6];
    const float* W3 = (const float*)d_in[7];
    const float* g3 = (const float*)d_in[8];
    const float* b3 = (const float*)d_in[9];
    float* out = (float*)d_out;

    prep_kernel<<<192, 256>>>(W2, W3);
    knn_kernel<<<dim3(BB, NN / 256), 256>>>(x);

    fgram_kernel<<<640, 256>>>(x);
    bn1fin_kernel<<<1, 256>>>(W1);

    h1pool_kernel<<<NPTS / 4, 256>>>(x, W1, g1, b1);

    h1gram_kernel<<<640, 256>>>(x, W1, g1, b1);
    gram2fin_kernel<<<65, 256>>>();
    bn2fin_kernel<<<128, 64>>>();

    gemm2pool_kernel<<<M1 / 160, 256>>>(x, W1, g1, b1, g2, b2);

    catgram_kernel<<<128, 256>>>();
    gram3fin_kernel<<<145, 256>>>();
    bn3fin_kernel<<<256, 192>>>();

    gemm3out_kernel<<<dim3(NPTS / 128, 2), 256>>>(g3, b3, out);

    (void)in_sizes; (void)n_in; (void)out_size;
}

// round 8
// speedup vs baseline: 2.0301x; 1.1212x over previous
#include <cuda_runtime.h>
#include <cuda_bf16.h>
#include <cstdint>

#define BB    8
#define NN    4096
#define KNB   20
#define NPTS  (BB * NN)          /* 32768  */
#define M1    (NPTS * KNB)       /* 655360 */
#define EPSB  1e-5f

/* ================= static device scratch (no allocations) ============= */
__device__ int   g_idx[M1];                         /* knn indices          */
__device__ float g_cat[(size_t)NPTS * 192];         /* [x1|x2] [P,192]      */
__device__ float g_w2t[64 * 128];                   /* W2^T [k][o]          */
__device__ float g_w3t[192 * 256];                  /* W3^T [k][o]          */
__device__ __nv_bfloat16 g_w2hi[128 * 64];          /* W2 bf16 hi [o][k]    */
__device__ __nv_bfloat16 g_w2lo[128 * 64];          /* W2 bf16 lo [o][k]    */
__device__ float g_fpart[640 * 27];                 /* feat gram partials   */
__device__ float g_colpart[64 * 8192];              /* h1 colsum partials   */
__device__ float g_gpart[(size_t)640 * 4096];       /* h1 gram partials     */
__device__ float g_gram[4096];                      /* h1 gram 64x64        */
__device__ float g_h1colsum[64];
__device__ float g_cpart[(size_t)128 * 36864];      /* cat gram partials    */
__device__ float g_cspart[128 * 192];               /* cat colsum partials  */
__device__ float g_cgram[36864];                    /* cat gram 192x192     */
__device__ float g_catsum[192];
__device__ float g_mu[448];                         /* L1:0 L2:64 L3:192    */
__device__ float g_rs[448];

/* ================= f32x2 packed-math helpers ========================= */
__device__ __forceinline__ double pack2(float x, float y) {
    double d;
    asm("mov.b64 %0, {%1, %2};" : "=d"(d) : "f"(x), "f"(y));
    return d;
}
__device__ __forceinline__ float2 unpack2(double d) {
    float2 r;
    asm("mov.b64 {%0, %1}, %2;" : "=f"(r.x), "=f"(r.y) : "d"(d));
    return r;
}
__device__ __forceinline__ double ffma2(double a, double b, double c) {
    double d;
    asm("fma.rn.f32x2 %0, %1, %2, %3;" : "=d"(d) : "d"(a), "d"(b), "d"(c));
    return d;
}

/* ================= mma.sync / ldmatrix helpers (plain PTX ISA) ======= */
__device__ __forceinline__ uint32_t smem_u32(const void* p) {
    uint32_t a;
    asm("{ .reg .u64 t; cvta.to.shared.u64 t, %1; cvt.u32.u64 %0, t; }"
        : "=r"(a) : "l"(p));
    return a;
}
__device__ __forceinline__ void ldsm_x4(uint32_t* r, uint32_t addr) {
    asm volatile("ldmatrix.sync.aligned.m8n8.x4.shared.b16 {%0,%1,%2,%3}, [%4];"
                 : "=r"(r[0]), "=r"(r[1]), "=r"(r[2]), "=r"(r[3]) : "r"(addr));
}
__device__ __forceinline__ void ldsm_x2(uint32_t* r, uint32_t addr) {
    asm volatile("ldmatrix.sync.aligned.m8n8.x2.shared.b16 {%0,%1}, [%2];"
                 : "=r"(r[0]), "=r"(r[1]) : "r"(addr));
}
__device__ __forceinline__ void mma_bf16(float* d, const uint32_t* a,
                                         const uint32_t* b) {
    asm volatile(
        "mma.sync.aligned.m16n8k16.row.col.f32.bf16.bf16.f32 "
        "{%0,%1,%2,%3}, {%4,%5,%6,%7}, {%8,%9}, {%0,%1,%2,%3};"
        : "+f"(d[0]), "+f"(d[1]), "+f"(d[2]), "+f"(d[3])
        : "r"(a[0]), "r"(a[1]), "r"(a[2]), "r"(a[3]), "r"(b[0]), "r"(b[1]));
}

/* ================= prep: transpose W2, W3; split W2 bf16 ============= */
__global__ void prep_kernel(const float* __restrict__ W2,
                            const float* __restrict__ W3) {
    int t = blockIdx.x * blockDim.x + threadIdx.x;
    if (t < 64 * 128) {
        int k = t / 128, o = t % 128;
        g_w2t[t] = W2[o * 64 + k];
        float w = W2[t];            /* [o][k] row-major direct */
        __nv_bfloat16 hi = __float2bfloat16(w);
        g_w2hi[t] = hi;
        g_w2lo[t] = __float2bfloat16(w - __bfloat162float(hi));
    }
    if (t < 192 * 256) {
        int k = t / 256, o = t % 256;
        g_w3t[t] = W3[o * 192 + k];
    }
}

/* ================= kNN: branch-light buffered top-20 ================= */
#define KTILE 512
#define BUFSZ 64

__device__ __forceinline__ void ins20(float v, int id, float* s, int* si) {
    bool c[20];
#pragma unroll
    for (int t = 0; t < 20; ++t) c[t] = v > s[t];
#pragma unroll
    for (int t = 19; t >= 1; --t) {
        float nv = c[t - 1] ? s[t - 1] : v;
        int   ni = c[t - 1] ? si[t - 1] : id;
        s[t]  = c[t] ? nv : s[t];
        si[t] = c[t] ? ni : si[t];
    }
    s[0]  = c[0] ? v : s[0];
    si[0] = c[0] ? id : si[0];
}

__global__ void knn_kernel(const float* __restrict__ x) {
    __shared__ float4 pts[KTILE];
    const int b = blockIdx.x;
    const int n = blockIdx.y * blockDim.x + threadIdx.x;
    const float* xb = x + b * 3 * NN;
    const float qx = xb[n], qy = xb[NN + n], qz = xb[2 * NN + n];
    const float q2x = 2.f * qx, q2y = 2.f * qy, q2z = 2.f * qz;

    float s[20];
    int   si[20];
#pragma unroll
    for (int t = 0; t < 20; ++t) { s[t] = -3.0e38f; si[t] = 0; }
    float thr = -3.0e38f;

    float bufv[BUFSZ];
    int   bufi[BUFSZ];
    int   cnt = 0;

    for (int base = 0; base < NN; base += KTILE) {
        __syncthreads();
        for (int m = threadIdx.x; m < KTILE; m += blockDim.x) {
            float px = xb[base + m], py = xb[NN + base + m], pz = xb[2 * NN + base + m];
            pts[m] = make_float4(px, py, pz, fmaf(px, px, fmaf(py, py, pz * pz)));
        }
        __syncthreads();

        for (int g = 0; g < KTILE; g += 32) {
#pragma unroll
            for (int j = 0; j < 32; ++j) {
                float4 p = pts[g + j];
                float v = fmaf(q2x, p.x, fmaf(q2y, p.y, fmaf(q2z, p.z, -p.w)));
                if (v > thr) { bufv[cnt] = v; bufi[cnt] = base + g + j; ++cnt; }
            }
            if (__any_sync(0xffffffffu, cnt >= 32)) {
                int mx = cnt;
#pragma unroll
                for (int o = 16; o; o >>= 1)
                    mx = max(mx, __shfl_xor_sync(0xffffffffu, mx, o));
                for (int q = 0; q < mx; ++q) {
                    float v = (q < cnt) ? bufv[q] : -3.2e38f;
                    int   i = (q < cnt) ? bufi[q] : 0;
                    ins20(v, i, s, si);
                }
                cnt = 0;
                thr = s[19];
            }
        }
    }
    {
        int mx = cnt;
#pragma unroll
        for (int o = 16; o; o >>= 1)
            mx = max(mx, __shfl_xor_sync(0xffffffffu, mx, o));
        for (int q = 0; q < mx; ++q) {
            float v = (q < cnt) ? bufv[q] : -3.2e38f;
            int   i = (q < cnt) ? bufi[q] : 0;
            ins20(v, i, s, si);
        }
    }
    int* op = g_idx + (size_t)(b * NN + n) * KNB;
#pragma unroll
    for (int t = 0; t < 20; ++t) op[t] = si[t];
}

/* ================= feat Gram (6x6 sym = 21) + feat colsum (6) ======== */
__global__ void fgram_kernel(const float* __restrict__ x) {
    const int t = threadIdx.x;
    float s[27];
#pragma unroll
    for (int v = 0; v < 27; ++v) s[v] = 0.f;

    for (int e = 0; e < 4; ++e) {
        int m = blockIdx.x * 1024 + e * 256 + t;
        int p = m / KNB;
        int b = p >> 12, n = p & (NN - 1);
        const float* xb = x + b * 3 * NN;
        int nb = g_idx[m];
        float cx = xb[n], cy = xb[NN + n], cz = xb[2 * NN + n];
        float f[6];
        f[0] = xb[nb] - cx;
        f[1] = xb[NN + nb] - cy;
        f[2] = xb[2 * NN + nb] - cz;
        f[3] = cx; f[4] = cy; f[5] = cz;
        int u = 0;
#pragma unroll
        for (int i = 0; i < 6; ++i) {
            s[21 + i] += f[i];
#pragma unroll
            for (int j = 0; j <= i; ++j) s[u++] = fmaf(f[i], f[j], s[u]);
        }
    }
#pragma unroll
    for (int off = 16; off; off >>= 1)
#pragma unroll
        for (int v = 0; v < 27; ++v)
            s[v] += __shfl_xor_sync(0xffffffffu, s[v], off);

    __shared__ float sm[8][27];
    if ((t & 31) == 0)
#pragma unroll
        for (int v = 0; v < 27; ++v) sm[t >> 5][v] = s[v];
    __syncthreads();
    if (t < 27) {
        float a = 0.f;
#pragma unroll
        for (int w = 0; w < 8; ++w) a += sm[w][t];
        g_fpart[blockIdx.x * 27 + t] = a;
    }
}

/* ================= BN1 stats from feat Gram ========================== */
__global__ void bn1fin_kernel(const float* __restrict__ W1) {
    __shared__ float part[27][8];
    __shared__ float gf[27];
    const int t = threadIdx.x;
    if (t < 216) {
        int j = t / 8, sl = t % 8;
        float a = 0.f;
        for (int i = sl; i < 640; i += 8) a += g_fpart[i * 27 + j];
        part[j][sl] = a;
    }
    __syncthreads();
    if (t < 27) {
        float a = 0.f;
#pragma unroll
        for (int sl = 0; sl < 8; ++sl) a += part[t][sl];
        gf[t] = a;
    }
    __syncthreads();
    if (t < 64) {
        float w[6];
#pragma unroll
        for (int c = 0; c < 6; ++c) w[c] = W1[t * 6 + c];
        const float invM = 1.f / (float)M1;
        float mu = 0.f;
#pragma unroll
        for (int i = 0; i < 6; ++i) mu = fmaf(w[i], gf[21 + i], mu);
        mu *= invM;
        float q = 0.f;
#pragma unroll
        for (int i = 0; i < 6; ++i)
#pragma unroll
            for (int j = 0; j <= i; ++j) {
                float val = gf[i * (i + 1) / 2 + j];
                float c = w[i] * w[j] * val;
                q += (i == j) ? c : 2.f * c;
            }
        q *= invM;
        g_mu[t] = mu;
        g_rs[t] = rsqrtf(q - mu * mu + EPSB);
    }
}

/* ================= h1 pool -> x1 (+ h1 colsum partials) ============== */
__global__ void h1pool_kernel(const float* __restrict__ x,
                              const float* __restrict__ W1,
                              const float* __restrict__ g1,
                              const float* __restrict__ b1) {
    __shared__ float feat[80][6];
    __shared__ float red[4][64];
    const int t  = threadIdx.x;
    const int o  = t & 63;
    const int pl = t >> 6;

    if (t < 80) {
        int p = blockIdx.x * 4 + t / 20;
        int k = t % 20;
        int m = p * KNB + k;
        int b = p >> 12, n = p & (NN - 1);
        const float* xb = x + b * 3 * NN;
        int nb = g_idx[m];
        float cx = xb[n], cy = xb[NN + n], cz = xb[2 * NN + n];
        feat[t][0] = xb[nb] - cx;
        feat[t][1] = xb[NN + nb] - cy;
        feat[t][2] = xb[2 * NN + nb] - cz;
        feat[t][3] = cx; feat[t][4] = cy; feat[t][5] = cz;
    }
    __syncthreads();

    float wr[6];
#pragma unroll
    for (int c = 0; c < 6; ++c) wr[c] = W1[o * 6 + c];
    const float mu = g_mu[o], rs = g_rs[o], gg = g1[o], bb = b1[o];

    const int p = blockIdx.x * 4 + pl;

    float h[KNB];
    float hmax = 0.f, cs = 0.f;
#pragma unroll
    for (int k = 0; k < KNB; ++k) {
        const float* f = feat[pl * KNB + k];
        float y = wr[0] * f[0];
        y = fmaf(wr[1], f[1], y);
        y = fmaf(wr[2], f[2], y);
        y = fmaf(wr[3], f[3], y);
        y = fmaf(wr[4], f[4], y);
        y = fmaf(wr[5], f[5], y);
        float hv = fmaxf(fmaf((y - mu) * rs, gg, bb), 0.f);
        h[k] = hv;
        hmax = fmaxf(hmax, hv);
        cs += hv;
    }
    float se = 0.f, sw = 0.f;
#pragma unroll
    for (int k = 0; k < KNB; ++k) {
        float e = __expf(h[k] - hmax);
        se += e;
        sw = fmaf(e, h[k], sw);
    }
    g_cat[(size_t)p * 192 + o] = sw / se;

    red[pl][o] = cs;
    __syncthreads();
    if (pl == 0)
        g_colpart[(size_t)o * 8192 + blockIdx.x] =
            red[0][o] + red[1][o] + red[2][o] + red[3][o];
}

/* ================= h1 Gram (64x64) partials, h1 recomputed =========== */
__global__ __launch_bounds__(256) void h1gram_kernel(
        const float* __restrict__ x,  const float* __restrict__ W1,
        const float* __restrict__ g1, const float* __restrict__ b1) {
    __shared__ float hs[32][68];
    __shared__ float f6[2][32][8];
    const int t = threadIdx.x;
    const int i16 = t & 15, j16 = t >> 4;
    const int c  = t & 63;
    const int rg = t >> 6;

    float wr[6];
#pragma unroll
    for (int j = 0; j < 6; ++j) wr[j] = W1[c * 6 + j];
    const float mu = g_mu[c], rsv = g_rs[c], gg = g1[c], bb = b1[c];

    double acc[4][2];
#pragma unroll
    for (int i = 0; i < 4; ++i) { acc[i][0] = 0.0; acc[i][1] = 0.0; }

    if (t < 32) {
        int m = blockIdx.x * 1024 + t;
        int p = m / KNB, b_ = p >> 12, n_ = p & (NN - 1);
        const float* xb = x + b_ * 3 * NN;
        int nb = g_idx[m];
        float cx = xb[n_], cy = xb[NN + n_], cz = xb[2 * NN + n_];
        f6[0][t][0] = xb[nb] - cx;
        f6[0][t][1] = xb[NN + nb] - cy;
        f6[0][t][2] = xb[2 * NN + nb] - cz;
        f6[0][t][3] = cx; f6[0][t][4] = cy; f6[0][t][5] = cz;
    }

    for (int cc = 0; cc < 32; ++cc) {
        const int cur = cc & 1;
        __syncthreads();

        if (cc + 1 < 32 && t < 32) {
            int m = blockIdx.x * 1024 + (cc + 1) * 32 + t;
            int p = m / KNB, b_ = p >> 12, n_ = p & (NN - 1);
            const float* xb = x + b_ * 3 * NN;
            int nb = g_idx[m];
            float cx = xb[n_], cy = xb[NN + n_], cz = xb[2 * NN + n_];
            f6[cur ^ 1][t][0] = xb[nb] - cx;
            f6[cur ^ 1][t][1] = xb[NN + nb] - cy;
            f6[cur ^ 1][t][2] = xb[2 * NN + nb] - cz;
            f6[cur ^ 1][t][3] = cx; f6[cur ^ 1][t][4] = cy; f6[cur ^ 1][t][5] = cz;
        }

#pragma unroll
        for (int rr = 0; rr < 8; ++rr) {
            const int r = rg + rr * 4;
            const float* f = f6[cur][r];
            float y = wr[0] * f[0];
            y = fmaf(wr[1], f[1], y);
            y = fmaf(wr[2], f[2], y);
            y = fmaf(wr[3], f[3], y);
            y = fmaf(wr[4], f[4], y);
            y = fmaf(wr[5], f[5], y);
            hs[r][c] = fmaxf(fmaf((y - mu) * rsv, gg, bb), 0.f);
        }
        __syncthreads();

#pragma unroll 8
        for (int r = 0; r < 32; ++r) {
            float4 a = *(const float4*)&hs[r][i16 * 4];
            double b0 = *(const double*)&hs[r][j16 * 4];
            double b1d = *(const double*)&hs[r][j16 * 4 + 2];
            const float av[4] = {a.x, a.y, a.z, a.w};
#pragma unroll
            for (int i = 0; i < 4; ++i) {
                double a2 = pack2(av[i], av[i]);
                acc[i][0] = ffma2(a2, b0, acc[i][0]);
                acc[i][1] = ffma2(a2, b1d, acc[i][1]);
            }
        }
    }
    float* gp = g_gpart + (size_t)blockIdx.x * 4096;
#pragma unroll
    for (int i = 0; i < 4; ++i) {
        float2 c0 = unpack2(acc[i][0]);
        float2 c1 = unpack2(acc[i][1]);
        float4 v = make_float4(c0.x, c0.y, c1.x, c1.y);
        *(float4*)(gp + (i16 * 4 + i) * 64 + j16 * 4) = v;
    }
}

/* ================= reduce h1 gram + colsum =========================== */
__global__ void gram2fin_kernel() {
    __shared__ float red[64][4];
    const int t = threadIdx.x;
    const int e = t >> 2, sl = t & 3;
    if (blockIdx.x == 64) {
        float a = 0.f;
        for (int i = sl; i < 8192; i += 4) a += g_colpart[(size_t)e * 8192 + i];
        red[e][sl] = a;
        __syncthreads();
        if (sl == 0)
            g_h1colsum[e] = red[e][0] + red[e][1] + red[e][2] + red[e][3];
        return;
    }
    const int ge = blockIdx.x * 64 + e;
    float a = 0.f;
    for (int i = sl; i < 640; i += 4) a += g_gpart[(size_t)i * 4096 + ge];
    red[e][sl] = a;
    __syncthreads();
    if (sl == 0)
        g_gram[ge] = red[e][0] + red[e][1] + red[e][2] + red[e][3];
}

/* ================= BN2 stats from h1 Gram ============================ */
__global__ void bn2fin_kernel() {
    const int o = blockIdx.x;
    const int i = threadIdx.x;
    __shared__ float w[64], rq[64], rm[64];
    w[i] = g_w2t[i * 128 + o];
    __syncthreads();
    float qi = 0.f;
    const float* Gi = g_gram + i * 64;
#pragma unroll 8
    for (int j = 0; j < 64; ++j) qi = fmaf(Gi[j], w[j], qi);
    rq[i] = qi * w[i];
    rm[i] = w[i] * g_h1colsum[i];
    __syncthreads();
    for (int s = 32; s > 0; s >>= 1) {
        if (i < s) { rq[i] += rq[i + s]; rm[i] += rm[i + s]; }
        __syncthreads();
    }
    if (i == 0) {
        const float invM = 1.f / (float)M1;
        float mu = rm[0] * invM;
        float var = rq[0] * invM - mu * mu;
        g_mu[64 + o] = mu;
        g_rs[64 + o] = rsqrtf(var + EPSB);
    }
}

/* ================= GEMM2 via mma.sync bf16 hi/lo + pool ============== */
/* Block: 160 edges (8 points) x 128 chans.  Warp w owns 16 chans.      */
/* A = W2 [chan][k] bf16 (rows padded to 144B), resident in frags.      */
/* B = h1 [edge][k] bf16 hi/lo (144B rows), ldmatrix.x2 (k-major = col).*/
/* D[chan][edge] staged per 40-edge group to warp slab -> BN+pool.      */
#define G2_ROWB   144
#define G2_OFF_F6   0
#define G2_OFF_WHI  5120
#define G2_OFF_WLO  (G2_OFF_WHI + 128 * G2_ROWB)
#define G2_OFF_BHI  (G2_OFF_WLO + 128 * G2_ROWB)
#define G2_OFF_BLO  (G2_OFF_BHI + 160 * G2_ROWB)
#define G2_OFF_SLAB (G2_OFF_BLO + 160 * G2_ROWB)
#define G2_SLABW    (16 * 44 * 4)                 /* per-warp slab bytes */
#define G2_SMEM     (G2_OFF_SLAB + 8 * G2_SLABW)

__global__ __launch_bounds__(256) void gemm2pool_hmma(
        const float* __restrict__ x,  const float* __restrict__ W1,
        const float* __restrict__ g1, const float* __restrict__ b1,
        const float* __restrict__ g2, const float* __restrict__ b2v) {
    extern __shared__ __align__(16) char smem[];
    const int t = threadIdx.x;
    const int w = t >> 5, lane = t & 31;
    const uint32_t sbase = smem_u32(smem);
    float* f6 = (float*)(smem + G2_OFF_F6);

    /* gather feat rows for 160 edges */
    if (t < 160) {
        int m = blockIdx.x * 160 + t;
        int p = m / KNB, b_ = p >> 12, n_ = p & (NN - 1);
        const float* xb = x + b_ * 3 * NN;
        int nb = g_idx[m];
        float cx = xb[n_], cy = xb[NN + n_], cz = xb[2 * NN + n_];
        f6[t * 8 + 0] = xb[nb] - cx;
        f6[t * 8 + 1] = xb[NN + nb] - cy;
        f6[t * 8 + 2] = xb[2 * NN + nb] - cz;
        f6[t * 8 + 3] = cx; f6[t * 8 + 4] = cy; f6[t * 8 + 5] = cz;
    }
    /* copy W2 hi/lo into padded-row smem (1024 chunks of 16B each) */
#pragma unroll
    for (int l = 0; l < 4; ++l) {
        int q = t + 256 * l;
        int r = q >> 3, c16 = q & 7;
        *(uint4*)(smem + G2_OFF_WHI + r * G2_ROWB + c16 * 16) = ((const uint4*)g_w2hi)[q];
        *(uint4*)(smem + G2_OFF_WLO + r * G2_ROWB + c16 * 16) = ((const uint4*)g_w2lo)[q];
    }
    __syncthreads();

    /* build B (h1) hi/lo tiles: thread (c = t&63, eg = t>>6) */
    {
        const int c  = t & 63;
        const int eg = t >> 6;
        float wr[6];
#pragma unroll
        for (int j = 0; j < 6; ++j) wr[j] = W1[c * 6 + j];
        const float mu = g_mu[c], rsv = g_rs[c], gg = g1[c], bb = b1[c];
#pragma unroll 4
        for (int i = 0; i < 40; ++i) {
            const int e = eg + i * 4;
            const float* f = f6 + e * 8;
            float y = wr[0] * f[0];
            y = fmaf(wr[1], f[1], y);
            y = fmaf(wr[2], f[2], y);
            y = fmaf(wr[3], f[3], y);
            y = fmaf(wr[4], f[4], y);
            y = fmaf(wr[5], f[5], y);
            float h = fmaxf(fmaf((y - mu) * rsv, gg, bb), 0.f);
            __nv_bfloat16 hi = __float2bfloat16(h);
            __nv_bfloat16 lo = __float2bfloat16(h - __bfloat162float(hi));
            *(__nv_bfloat16*)(smem + G2_OFF_BHI + e * G2_ROWB + c * 2) = hi;
            *(__nv_bfloat16*)(smem + G2_OFF_BLO + e * G2_ROWB + c * 2) = lo;
        }
    }
    __syncthreads();

    /* load resident A fragments: chans cbase..cbase+15, 4 k-chunks, hi/lo */
    const int cbase = w * 16;
    uint32_t ahi[4][4], alo[4][4];
    {
        const uint32_t arow = (uint32_t)(cbase + (lane & 15)) * G2_ROWB
                            + ((lane >> 4) & 1) * 16;
#pragma unroll
        for (int kc = 0; kc < 4; ++kc) {
            ldsm_x4(ahi[kc], sbase + G2_OFF_WHI + arow + kc * 32);
            ldsm_x4(alo[kc], sbase + G2_OFF_WLO + arow + kc * 32);
        }
    }

    /* BN2 params for this thread's pooling channel */
    const int pch = cbase + (lane & 15);
    const float mu2 = g_mu[64 + pch], rs2 = g_rs[64 + pch];
    const float gg2 = g2[pch], bb2 = b2v[pch];
    float* slab = (float*)(smem + G2_OFF_SLAB + w * G2_SLABW);

    /* 4 groups x 5 n-tiles (40 edges = 2 points each) */
#pragma unroll
    for (int grp = 0; grp < 4; ++grp) {
        float D[5][4];
#pragma unroll
        for (int nt = 0; nt < 5; ++nt)
#pragma unroll
            for (int j = 0; j < 4; ++j) D[nt][j] = 0.f;

#pragma unroll
        for (int nt = 0; nt < 5; ++nt) {
            const int ebase = grp * 40 + nt * 8;
            const uint32_t brow = (uint32_t)(ebase + (lane & 7)) * G2_ROWB
                                + ((lane >> 3) & 1) * 16;
#pragma unroll
            for (int kc = 0; kc < 4; ++kc) {
                uint32_t bh[2], bl[2];
                ldsm_x2(bh, sbase + G2_OFF_BHI + brow + kc * 32);
                ldsm_x2(bl, sbase + G2_OFF_BLO + brow + kc * 32);
                mma_bf16(D[nt], ahi[kc], bh);
                mma_bf16(D[nt], ahi[kc], bl);
                mma_bf16(D[nt], alo[kc], bh);
            }
        }
        /* stage D to slab: rows = 16 chans (stride 44), cols = 40 edges */
        {
            const int r0 = lane >> 2;
            const int c0 = 2 * (lane & 3);
#pragma unroll
            for (int nt = 0; nt < 5; ++nt) {
                const int col = nt * 8 + c0;
                slab[r0 * 44 + col]           = D[nt][0];
                slab[r0 * 44 + col + 1]       = D[nt][1];
                slab[(r0 + 8) * 44 + col]     = D[nt][2];
                slab[(r0 + 8) * 44 + col + 1] = D[nt][3];
            }
        }
        __syncwarp();
        /* pool: lane -> (chan = lane&15, point-half = lane>>4) */
        {
            const int ch = lane & 15;
            const int ph = lane >> 4;
            const float* row = slab + ch * 44 + ph * 20;
            float h[20], hmax = 0.f;
#pragma unroll
            for (int k = 0; k < 20; ++k) {
                float y = row[k];
                h[k] = fmaxf(fmaf((y - mu2) * rs2, gg2, bb2), 0.f);
                hmax = fmaxf(hmax, h[k]);
            }
            float se = 0.f, sw = 0.f;
#pragma unroll
            for (int k = 0; k < 20; ++k) {
                float e = __expf(h[k] - hmax);
                se += e;
                sw = fmaf(e, h[k], sw);
            }
            const int p = blockIdx.x * 8 + grp * 2 + ph;
            g_cat[(size_t)p * 192 + 64 + pch] = sw / se;
        }
        __syncwarp();
    }
}

/* ================= cat Gram (192x192) + colsum ======================= */
__global__ __launch_bounds__(256) void catgram_kernel() {
    __shared__ float sm[16][196];
    const int t = threadIdx.x;
    const int i16 = t & 15, j16 = t >> 4;

    double acc[12][6];
#pragma unroll
    for (int i = 0; i < 12; ++i)
#pragma unroll
        for (int j = 0; j < 6; ++j) acc[i][j] = 0.0;
    float cs[12];
#pragma unroll
    for (int u = 0; u < 12; ++u) cs[u] = 0.f;

    for (int c = 0; c < 16; ++c) {
        const int rowbase = blockIdx.x * 256 + c * 16;
#pragma unroll
        for (int l = 0; l < 3; ++l) {
            int q = t + 256 * l;
            int r = q / 48, cq = (q % 48) * 4;
            *(float4*)&sm[r][cq] =
                *(const float4*)(g_cat + (size_t)(rowbase + r) * 192 + cq);
        }
        __syncthreads();
#pragma unroll 4
        for (int r = 0; r < 16; ++r) {
            float a[12];
#pragma unroll
            for (int u = 0; u < 6; ++u) {
                float2 pv = *(const float2*)&sm[r][i16 * 12 + 2 * u];
                a[2 * u] = pv.x; a[2 * u + 1] = pv.y;
            }
            double bd[6];
#pragma unroll
            for (int u = 0; u < 6; ++u)
                bd[u] = *(const double*)&sm[r][j16 * 12 + 2 * u];
#pragma unroll
            for (int i = 0; i < 12; ++i) {
                double a2 = pack2(a[i], a[i]);
#pragma unroll
                for (int j = 0; j < 6; ++j)
                    acc[i][j] = ffma2(a2, bd[j], acc[i][j]);
            }
            if (j16 == 0) {
#pragma unroll
                for (int u = 0; u < 12; ++u) cs[u] += a[u];
            }
        }
        __syncthreads();
    }
    float* cp = g_cpart + (size_t)blockIdx.x * 36864;
#pragma unroll
    for (int i = 0; i < 12; ++i) {
        float* row = cp + (i16 * 12 + i) * 192 + j16 * 12;
#pragma unroll
        for (int j = 0; j < 6; ++j) {
            float2 v = unpack2(acc[i][j]);
            *(float2*)(row + 2 * j) = v;
        }
    }
    if (j16 == 0) {
#pragma unroll
        for (int u = 0; u < 12; ++u)
            g_cspart[blockIdx.x * 192 + i16 * 12 + u] = cs[u];
    }
}

/* ================= reduce cat gram + colsum ========================== */
__global__ void gram3fin_kernel() {
    const int t = threadIdx.x;
    if (blockIdx.x == 144) {
        if (t < 192) {
            float a = 0.f;
            for (int p = 0; p < 128; ++p) a += g_cspart[p * 192 + t];
            g_catsum[t] = a;
        }
        return;
    }
    const int e = blockIdx.x * 256 + t;
    float a = 0.f;
    for (int p = 0; p < 128; ++p) a += g_cpart[(size_t)p * 36864 + e];
    g_cgram[e] = a;
}

/* ================= BN3 stats from cat Gram =========================== */
__global__ void bn3fin_kernel() {
    const int o = blockIdx.x;
    const int i = threadIdx.x;
    __shared__ float w[192], rq[192], rm[192];
    w[i] = g_w3t[i * 256 + o];
    __syncthreads();
    float qi = 0.f;
    const float* Gi = g_cgram + i * 192;
#pragma unroll 8
    for (int j = 0; j < 192; ++j) qi = fmaf(Gi[j], w[j], qi);
    rq[i] = qi * w[i];
    rm[i] = w[i] * g_catsum[i];
    __syncthreads();
    for (int s = 96; s >= 3; s >>= 1) {
        if (i < s) { rq[i] += rq[i + s]; rm[i] += rm[i + s]; }
        __syncthreads();
    }
    if (i == 0) {
        const float invN = 1.f / (float)NPTS;
        float mu = (rm[0] + rm[1] + rm[2]) * invN;
        float var = (rq[0] + rq[1] + rq[2]) * invN - mu * mu;
        g_mu[192 + o] = mu;
        g_rs[192 + o] = rsqrtf(var + EPSB);
    }
}

/* ================= GEMM3 + BN3 + ReLU + transposed write ============= */
__global__ __launch_bounds__(256) void gemm3out_kernel(
        const float* __restrict__ g3, const float* __restrict__ b3,
        float* __restrict__ out) {
    __shared__ float As[32][134];
    __shared__ float Bs[32][128];
    const int t = threadIdx.x;
    const int tx = t & 15, ty = t >> 4;
    const int mbase = blockIdx.x * 128;
    const int nbase = blockIdx.y * 128;

    double acc[8][4];
#pragma unroll
    for (int i = 0; i < 8; ++i)
#pragma unroll
        for (int j = 0; j < 4; ++j) acc[i][j] = 0.0;

    for (int kt = 0; kt < 192; kt += 32) {
#pragma unroll
        for (int l = 0; l < 4; ++l) {
            int q = t + 256 * l;
            int r = q >> 3, kq = (q & 7) << 2;
            float4 v = *(const float4*)(g_cat + (size_t)(mbase + r) * 192 + kt + kq);
            As[kq + 0][r] = v.x;
            As[kq + 1][r] = v.y;
            As[kq + 2][r] = v.z;
            As[kq + 3][r] = v.w;
        }
#pragma unroll
        for (int l = 0; l < 4; ++l) {
            int q = t + 256 * l;
            int kk = q >> 5, nn = (q & 31) << 2;
            *(float4*)&Bs[kk][nn] =
                *(const float4*)(g_w3t + (size_t)(kt + kk) * 256 + nbase + nn);
        }
        __syncthreads();
#pragma unroll 4
        for (int k = 0; k < 32; ++k) {
            double bd[4];
#pragma unroll
            for (int jd = 0; jd < 4; ++jd)
                bd[jd] = *(const double*)&Bs[k][2 * tx + 32 * jd];
            float a[8];
#pragma unroll
            for (int u = 0; u < 4; ++u) {
                float2 pv = *(const float2*)&As[k][2 * ty + 32 * u];
                a[2 * u] = pv.x; a[2 * u + 1] = pv.y;
            }
#pragma unroll
            for (int i = 0; i < 8; ++i) {
                double a2 = pack2(a[i], a[i]);
#pragma unroll
                for (int jd = 0; jd < 4; ++jd)
                    acc[i][jd] = ffma2(a2, bd[jd], acc[i][jd]);
            }
        }
        __syncthreads();
    }

    const int b = mbase >> 12;
    const int nloc = mbase & (NN - 1);
#pragma unroll
    for (int jd = 0; jd < 4; ++jd) {
#pragma unroll
        for (int half = 0; half < 2; ++half) {
            const int o = nbase + 32 * jd + 2 * tx + half;
            const float mu = g_mu[192 + o], rsv = g_rs[192 + o];
            const float gg = g3[o], bb = b3[o];
#pragma unroll
            for (int u = 0; u < 4; ++u) {
                float2 clo = unpack2(acc[2 * u][jd]);
                float2 chi = unpack2(acc[2 * u + 1][jd]);
                float y0 = half ? clo.y : clo.x;
                float y1 = half ? chi.y : chi.x;
                float v0 = fmaxf(fmaf((y0 - mu) * rsv, gg, bb), 0.f);
                float v1 = fmaxf(fmaf((y1 - mu) * rsv, gg, bb), 0.f);
                float* op = out + ((size_t)b * 256 + o) * NN
                                + nloc + 2 * ty + 32 * u;
                *(float2*)op = make_float2(v0, v1);
            }
        }
    }
}

/* ================= launcher ========================================== */
extern "C" void kernel_launch(void* const* d_in, const int* in_sizes, int n_in,
                              void* d_out, int out_size) {
    const float* x  = (const float*)d_in[0];
    const float* W1 = (const float*)d_in[1];
    const float* g1 = (const float*)d_in[2];
    const float* b1 = (const float*)d_in[3];
    const float* W2 = (const float*)d_in[4];
    const float* g2 = (const float*)d_in[5];
    const float* b2 = (const float*)d_in[6];
    const float* W3 = (const float*)d_in[7];
    const float* g3 = (const float*)d_in[8];
    const float* b3 = (const float*)d_in[9];
    float* out = (float*)d_out;

    cudaFuncSetAttribute(gemm2pool_hmma,
                         cudaFuncAttributeMaxDynamicSharedMemorySize, G2_SMEM);

    prep_kernel<<<192, 256>>>(W2, W3);
    knn_kernel<<<dim3(BB, NN / 256), 256>>>(x);

    fgram_kernel<<<640, 256>>>(x);
    bn1fin_kernel<<<1, 256>>>(W1);

    h1pool_kernel<<<NPTS / 4, 256>>>(x, W1, g1, b1);

    h1gram_kernel<<<640, 256>>>(x, W1, g1, b1);
    gram2fin_kernel<<<65, 256>>>();
    bn2fin_kernel<<<128, 64>>>();

    gemm2pool_hmma<<<M1 / 160, 256, G2_SMEM>>>(x, W1, g1, b1, g2, b2);

    catgram_kernel<<<128, 256>>>();
    gram3fin_kernel<<<145, 256>>>();
    bn3fin_kernel<<<256, 192>>>();

    gemm3out_kernel<<<dim3(NPTS / 128, 2), 256>>>(g3, b3, out);

    (void)in_sizes; (void)n_in; (void)out_size;
}

// round 9
// speedup vs baseline: 2.2719x; 1.1191x over previous
#include <cuda_runtime.h>
#include <cuda_bf16.h>
#include <cstdint>

#define BB    8
#define NN    4096
#define KNB   20
#define NPTS  (BB * NN)          /* 32768  */
#define M1    (NPTS * KNB)       /* 655360 */
#define EPSB  1e-5f

/* ================= static device scratch (no allocations) ============= */
__device__ int   g_idx[M1];                         /* knn indices          */
__device__ float g_cat[(size_t)NPTS * 192];         /* [x1|x2] [P,192]      */
__device__ float g_w2t[64 * 128];                   /* W2^T [k][o]          */
__device__ float g_w3t[192 * 256];                  /* W3^T [k][o]          */
__device__ __nv_bfloat16 g_w2hi[128 * 64];          /* W2 bf16 hi [o][k]    */
__device__ __nv_bfloat16 g_w2lo[128 * 64];          /* W2 bf16 lo [o][k]    */
__device__ __nv_bfloat16 g_w3hi[256 * 192];         /* W3 bf16 hi [o][k]    */
__device__ __nv_bfloat16 g_w3lo[256 * 192];         /* W3 bf16 lo [o][k]    */
__device__ float g_fpart[640 * 27];                 /* feat gram partials   */
__device__ float g_colpart[64 * 8192];              /* h1 colsum partials   */
__device__ float g_gpart[(size_t)640 * 4096];       /* h1 gram partials     */
__device__ float g_gram[4096];                      /* h1 gram 64x64        */
__device__ float g_h1colsum[64];
__device__ float g_cpart[(size_t)128 * 36864];      /* cat gram partials    */
__device__ float g_cspart[128 * 192];               /* cat colsum partials  */
__device__ float g_cgram[36864];                    /* cat gram 192x192     */
__device__ float g_catsum[192];
__device__ float g_mu[448];                         /* L1:0 L2:64 L3:192    */
__device__ float g_rs[448];

/* ================= f32x2 packed-math helpers ========================= */
__device__ __forceinline__ double pack2(float x, float y) {
    double d;
    asm("mov.b64 %0, {%1, %2};" : "=d"(d) : "f"(x), "f"(y));
    return d;
}
__device__ __forceinline__ float2 unpack2(double d) {
    float2 r;
    asm("mov.b64 {%0, %1}, %2;" : "=f"(r.x), "=f"(r.y) : "d"(d));
    return r;
}
__device__ __forceinline__ double ffma2(double a, double b, double c) {
    double d;
    asm("fma.rn.f32x2 %0, %1, %2, %3;" : "=d"(d) : "d"(a), "d"(b), "d"(c));
    return d;
}

/* ================= mma.sync / ldmatrix helpers (plain PTX ISA) ======= */
__device__ __forceinline__ uint32_t smem_u32(const void* p) {
    uint32_t a;
    asm("{ .reg .u64 t; cvta.to.shared.u64 t, %1; cvt.u32.u64 %0, t; }"
        : "=r"(a) : "l"(p));
    return a;
}
__device__ __forceinline__ void ldsm_x4(uint32_t* r, uint32_t addr) {
    asm volatile("ldmatrix.sync.aligned.m8n8.x4.shared.b16 {%0,%1,%2,%3}, [%4];"
                 : "=r"(r[0]), "=r"(r[1]), "=r"(r[2]), "=r"(r[3]) : "r"(addr));
}
__device__ __forceinline__ void ldsm_x2(uint32_t* r, uint32_t addr) {
    asm volatile("ldmatrix.sync.aligned.m8n8.x2.shared.b16 {%0,%1}, [%2];"
                 : "=r"(r[0]), "=r"(r[1]) : "r"(addr));
}
__device__ __forceinline__ void mma_bf16(float* d, const uint32_t* a,
                                         const uint32_t* b) {
    asm volatile(
        "mma.sync.aligned.m16n8k16.row.col.f32.bf16.bf16.f32 "
        "{%0,%1,%2,%3}, {%4,%5,%6,%7}, {%8,%9}, {%0,%1,%2,%3};"
        : "+f"(d[0]), "+f"(d[1]), "+f"(d[2]), "+f"(d[3])
        : "r"(a[0]), "r"(a[1]), "r"(a[2]), "r"(a[3]), "r"(b[0]), "r"(b[1]));
}
/* pack 4 floats -> 4 bf16 (hi) and 4 bf16 (lo of residual) */
__device__ __forceinline__ void split4(float4 v, uint2* hi, uint2* lo) {
    __nv_bfloat16 hx = __float2bfloat16(v.x), hy = __float2bfloat16(v.y);
    __nv_bfloat16 hz = __float2bfloat16(v.z), hw = __float2bfloat16(v.w);
    __nv_bfloat16 lx = __float2bfloat16(v.x - __bfloat162float(hx));
    __nv_bfloat16 ly = __float2bfloat16(v.y - __bfloat162float(hy));
    __nv_bfloat16 lz = __float2bfloat16(v.z - __bfloat162float(hz));
    __nv_bfloat16 lw = __float2bfloat16(v.w - __bfloat162float(hw));
    __nv_bfloat162 h01, h23, l01, l23;
    h01.x = hx; h01.y = hy; h23.x = hz; h23.y = hw;
    l01.x = lx; l01.y = ly; l23.x = lz; l23.y = lw;
    hi->x = *(uint32_t*)&h01; hi->y = *(uint32_t*)&h23;
    lo->x = *(uint32_t*)&l01; lo->y = *(uint32_t*)&l23;
}

/* ================= prep: transposes + bf16 splits ==================== */
__global__ void prep_kernel(const float* __restrict__ W2,
                            const float* __restrict__ W3) {
    int t = blockIdx.x * blockDim.x + threadIdx.x;
    if (t < 64 * 128) {
        int k = t / 128, o = t % 128;
        g_w2t[t] = W2[o * 64 + k];
        float w = W2[t];
        __nv_bfloat16 hi = __float2bfloat16(w);
        g_w2hi[t] = hi;
        g_w2lo[t] = __float2bfloat16(w - __bfloat162float(hi));
    }
    if (t < 192 * 256) {
        int k = t / 256, o = t % 256;
        g_w3t[t] = W3[o * 192 + k];
        float w = W3[t];            /* [o][k] row-major direct */
        __nv_bfloat16 hi = __float2bfloat16(w);
        g_w3hi[t] = hi;
        g_w3lo[t] = __float2bfloat16(w - __bfloat162float(hi));
    }
}

/* ================= kNN: branch-light buffered top-20 ================= */
#define KTILE 512
#define BUFSZ 64

__device__ __forceinline__ void ins20(float v, int id, float* s, int* si) {
    bool c[20];
#pragma unroll
    for (int t = 0; t < 20; ++t) c[t] = v > s[t];
#pragma unroll
    for (int t = 19; t >= 1; --t) {
        float nv = c[t - 1] ? s[t - 1] : v;
        int   ni = c[t - 1] ? si[t - 1] : id;
        s[t]  = c[t] ? nv : s[t];
        si[t] = c[t] ? ni : si[t];
    }
    s[0]  = c[0] ? v : s[0];
    si[0] = c[0] ? id : si[0];
}

__global__ void knn_kernel(const float* __restrict__ x) {
    __shared__ float4 pts[KTILE];
    const int b = blockIdx.x;
    const int n = blockIdx.y * blockDim.x + threadIdx.x;
    const float* xb = x + b * 3 * NN;
    const float qx = xb[n], qy = xb[NN + n], qz = xb[2 * NN + n];
    const float q2x = 2.f * qx, q2y = 2.f * qy, q2z = 2.f * qz;

    float s[20];
    int   si[20];
#pragma unroll
    for (int t = 0; t < 20; ++t) { s[t] = -3.0e38f; si[t] = 0; }
    float thr = -3.0e38f;

    float bufv[BUFSZ];
    int   bufi[BUFSZ];
    int   cnt = 0;

    for (int base = 0; base < NN; base += KTILE) {
        __syncthreads();
        for (int m = threadIdx.x; m < KTILE; m += blockDim.x) {
            float px = xb[base + m], py = xb[NN + base + m], pz = xb[2 * NN + base + m];
            pts[m] = make_float4(px, py, pz, fmaf(px, px, fmaf(py, py, pz * pz)));
        }
        __syncthreads();

        for (int g = 0; g < KTILE; g += 32) {
#pragma unroll
            for (int j = 0; j < 32; ++j) {
                float4 p = pts[g + j];
                float v = fmaf(q2x, p.x, fmaf(q2y, p.y, fmaf(q2z, p.z, -p.w)));
                if (v > thr) { bufv[cnt] = v; bufi[cnt] = base + g + j; ++cnt; }
            }
            if (__any_sync(0xffffffffu, cnt >= 32)) {
                int mx = cnt;
#pragma unroll
                for (int o = 16; o; o >>= 1)
                    mx = max(mx, __shfl_xor_sync(0xffffffffu, mx, o));
                for (int q = 0; q < mx; ++q) {
                    float v = (q < cnt) ? bufv[q] : -3.2e38f;
                    int   i = (q < cnt) ? bufi[q] : 0;
                    ins20(v, i, s, si);
                }
                cnt = 0;
                thr = s[19];
            }
        }
    }
    {
        int mx = cnt;
#pragma unroll
        for (int o = 16; o; o >>= 1)
            mx = max(mx, __shfl_xor_sync(0xffffffffu, mx, o));
        for (int q = 0; q < mx; ++q) {
            float v = (q < cnt) ? bufv[q] : -3.2e38f;
            int   i = (q < cnt) ? bufi[q] : 0;
            ins20(v, i, s, si);
        }
    }
    int* op = g_idx + (size_t)(b * NN + n) * KNB;
#pragma unroll
    for (int t = 0; t < 20; ++t) op[t] = si[t];
}

/* ================= feat Gram (6x6 sym = 21) + feat colsum (6) ======== */
__global__ void fgram_kernel(const float* __restrict__ x) {
    const int t = threadIdx.x;
    float s[27];
#pragma unroll
    for (int v = 0; v < 27; ++v) s[v] = 0.f;

    for (int e = 0; e < 4; ++e) {
        int m = blockIdx.x * 1024 + e * 256 + t;
        int p = m / KNB;
        int b = p >> 12, n = p & (NN - 1);
        const float* xb = x + b * 3 * NN;
        int nb = g_idx[m];
        float cx = xb[n], cy = xb[NN + n], cz = xb[2 * NN + n];
        float f[6];
        f[0] = xb[nb] - cx;
        f[1] = xb[NN + nb] - cy;
        f[2] = xb[2 * NN + nb] - cz;
        f[3] = cx; f[4] = cy; f[5] = cz;
        int u = 0;
#pragma unroll
        for (int i = 0; i < 6; ++i) {
            s[21 + i] += f[i];
#pragma unroll
            for (int j = 0; j <= i; ++j) s[u++] = fmaf(f[i], f[j], s[u]);
        }
    }
#pragma unroll
    for (int off = 16; off; off >>= 1)
#pragma unroll
        for (int v = 0; v < 27; ++v)
            s[v] += __shfl_xor_sync(0xffffffffu, s[v], off);

    __shared__ float sm[8][27];
    if ((t & 31) == 0)
#pragma unroll
        for (int v = 0; v < 27; ++v) sm[t >> 5][v] = s[v];
    __syncthreads();
    if (t < 27) {
        float a = 0.f;
#pragma unroll
        for (int w = 0; w < 8; ++w) a += sm[w][t];
        g_fpart[blockIdx.x * 27 + t] = a;
    }
}

/* ================= BN1 stats from feat Gram ========================== */
__global__ void bn1fin_kernel(const float* __restrict__ W1) {
    __shared__ float part[27][8];
    __shared__ float gf[27];
    const int t = threadIdx.x;
    if (t < 216) {
        int j = t / 8, sl = t % 8;
        float a = 0.f;
        for (int i = sl; i < 640; i += 8) a += g_fpart[i * 27 + j];
        part[j][sl] = a;
    }
    __syncthreads();
    if (t < 27) {
        float a = 0.f;
#pragma unroll
        for (int sl = 0; sl < 8; ++sl) a += part[t][sl];
        gf[t] = a;
    }
    __syncthreads();
    if (t < 64) {
        float w[6];
#pragma unroll
        for (int c = 0; c < 6; ++c) w[c] = W1[t * 6 + c];
        const float invM = 1.f / (float)M1;
        float mu = 0.f;
#pragma unroll
        for (int i = 0; i < 6; ++i) mu = fmaf(w[i], gf[21 + i], mu);
        mu *= invM;
        float q = 0.f;
#pragma unroll
        for (int i = 0; i < 6; ++i)
#pragma unroll
            for (int j = 0; j <= i; ++j) {
                float val = gf[i * (i + 1) / 2 + j];
                float c = w[i] * w[j] * val;
                q += (i == j) ? c : 2.f * c;
            }
        q *= invM;
        g_mu[t] = mu;
        g_rs[t] = rsqrtf(q - mu * mu + EPSB);
    }
}

/* ================= h1 pool -> x1 (+ h1 colsum partials) ============== */
__global__ void h1pool_kernel(const float* __restrict__ x,
                              const float* __restrict__ W1,
                              const float* __restrict__ g1,
                              const float* __restrict__ b1) {
    __shared__ float feat[80][6];
    __shared__ float red[4][64];
    const int t  = threadIdx.x;
    const int o  = t & 63;
    const int pl = t >> 6;

    if (t < 80) {
        int p = blockIdx.x * 4 + t / 20;
        int k = t % 20;
        int m = p * KNB + k;
        int b = p >> 12, n = p & (NN - 1);
        const float* xb = x + b * 3 * NN;
        int nb = g_idx[m];
        float cx = xb[n], cy = xb[NN + n], cz = xb[2 * NN + n];
        feat[t][0] = xb[nb] - cx;
        feat[t][1] = xb[NN + nb] - cy;
        feat[t][2] = xb[2 * NN + nb] - cz;
        feat[t][3] = cx; feat[t][4] = cy; feat[t][5] = cz;
    }
    __syncthreads();

    float wr[6];
#pragma unroll
    for (int c = 0; c < 6; ++c) wr[c] = W1[o * 6 + c];
    const float mu = g_mu[o], rs = g_rs[o], gg = g1[o], bb = b1[o];

    const int p = blockIdx.x * 4 + pl;

    float h[KNB];
    float hmax = 0.f, cs = 0.f;
#pragma unroll
    for (int k = 0; k < KNB; ++k) {
        const float* f = feat[pl * KNB + k];
        float y = wr[0] * f[0];
        y = fmaf(wr[1], f[1], y);
        y = fmaf(wr[2], f[2], y);
        y = fmaf(wr[3], f[3], y);
        y = fmaf(wr[4], f[4], y);
        y = fmaf(wr[5], f[5], y);
        float hv = fmaxf(fmaf((y - mu) * rs, gg, bb), 0.f);
        h[k] = hv;
        hmax = fmaxf(hmax, hv);
        cs += hv;
    }
    float se = 0.f, sw = 0.f;
#pragma unroll
    for (int k = 0; k < KNB; ++k) {
        float e = __expf(h[k] - hmax);
        se += e;
        sw = fmaf(e, h[k], sw);
    }
    g_cat[(size_t)p * 192 + o] = sw / se;

    red[pl][o] = cs;
    __syncthreads();
    if (pl == 0)
        g_colpart[(size_t)o * 8192 + blockIdx.x] =
            red[0][o] + red[1][o] + red[2][o] + red[3][o];
}

/* ================= h1 Gram (64x64) via HMMA hi/lo ==================== */
/* Block = 1024 edges. Transposed tile T[64 chan][64 edge] bf16 hi/lo.   */
/* D[c1][c2] += sum_e T[c1][e] T[c2][e]; warp w: m = (w&3)*16,           */
/* n = (w>>2)*32 (4 n-subtiles). 3 passes: HH, HL, LH (symmetric).       */
#define HG_ROWB 144
__global__ __launch_bounds__(256) void h1gram_hmma(
        const float* __restrict__ x,  const float* __restrict__ W1,
        const float* __restrict__ g1, const float* __restrict__ b1) {
    __shared__ float f6[2][64][8];
    __shared__ __align__(16) char thi[64 * HG_ROWB];
    __shared__ __align__(16) char tlo[64 * HG_ROWB];
    const int t = threadIdx.x;
    const int w = t >> 5, lane = t & 31;
    const uint32_t uthi = smem_u32(thi), utlo = smem_u32(tlo);
    const int mrow = (w & 3) * 16;
    const int ncol = (w >> 2) * 32;

    const int c  = t & 63;
    const int eg = t >> 6;
    float wr[6];
#pragma unroll
    for (int j = 0; j < 6; ++j) wr[j] = W1[c * 6 + j];
    const float mu = g_mu[c], rsv = g_rs[c], gg = g1[c], bb = b1[c];

    float acc[4][4];
#pragma unroll
    for (int i = 0; i < 4; ++i)
#pragma unroll
        for (int j = 0; j < 4; ++j) acc[i][j] = 0.f;

    /* prime chunk-0 feat */
    if (t < 64) {
        int m = blockIdx.x * 1024 + t;
        int p = m / KNB, b_ = p >> 12, n_ = p & (NN - 1);
        const float* xb = x + b_ * 3 * NN;
        int nb = g_idx[m];
        float cx = xb[n_], cy = xb[NN + n_], cz = xb[2 * NN + n_];
        f6[0][t][0] = xb[nb] - cx;
        f6[0][t][1] = xb[NN + nb] - cy;
        f6[0][t][2] = xb[2 * NN + nb] - cz;
        f6[0][t][3] = cx; f6[0][t][4] = cy; f6[0][t][5] = cz;
    }

    for (int cc = 0; cc < 16; ++cc) {
        const int cur = cc & 1;
        __syncthreads();   /* f6[cur] ready; T free */
        if (cc + 1 < 16 && t < 64) {
            int m = blockIdx.x * 1024 + (cc + 1) * 64 + t;
            int p = m / KNB, b_ = p >> 12, n_ = p & (NN - 1);
            const float* xb = x + b_ * 3 * NN;
            int nb = g_idx[m];
            float cx = xb[n_], cy = xb[NN + n_], cz = xb[2 * NN + n_];
            f6[cur ^ 1][t][0] = xb[nb] - cx;
            f6[cur ^ 1][t][1] = xb[NN + nb] - cy;
            f6[cur ^ 1][t][2] = xb[2 * NN + nb] - cz;
            f6[cur ^ 1][t][3] = cx; f6[cur ^ 1][t][4] = cy; f6[cur ^ 1][t][5] = cz;
        }
        /* fill T[c][e] for e = eg, eg+4, ..., 16 values */
#pragma unroll 4
        for (int i = 0; i < 16; ++i) {
            const int e = eg + i * 4;
            const float* f = f6[cur][e];
            float y = wr[0] * f[0];
            y = fmaf(wr[1], f[1], y);
            y = fmaf(wr[2], f[2], y);
            y = fmaf(wr[3], f[3], y);
            y = fmaf(wr[4], f[4], y);
            y = fmaf(wr[5], f[5], y);
            float h = fmaxf(fmaf((y - mu) * rsv, gg, bb), 0.f);
            __nv_bfloat16 hi = __float2bfloat16(h);
            __nv_bfloat16 lo = __float2bfloat16(h - __bfloat162float(hi));
            *(__nv_bfloat16*)(thi + c * HG_ROWB + e * 2) = hi;
            *(__nv_bfloat16*)(tlo + c * HG_ROWB + e * 2) = lo;
        }
        __syncthreads();   /* T ready */

#pragma unroll
        for (int ks = 0; ks < 4; ++ks) {
            const uint32_t aoff = (uint32_t)(mrow + (lane & 15)) * HG_ROWB
                                + ((lane >> 4) & 1) * 16 + ks * 32;
            uint32_t ah[4], al[4];
            ldsm_x4(ah, uthi + aoff);
            ldsm_x4(al, utlo + aoff);
#pragma unroll
            for (int nt = 0; nt < 4; ++nt) {
                const uint32_t boff =
                    (uint32_t)(ncol + nt * 8 + (lane & 7)) * HG_ROWB
                    + ((lane >> 3) & 1) * 16 + ks * 32;
                uint32_t bh[2], bl[2];
                ldsm_x2(bh, uthi + boff);
                ldsm_x2(bl, utlo + boff);
                mma_bf16(acc[nt], ah, bh);
                mma_bf16(acc[nt], ah, bl);
                mma_bf16(acc[nt], al, bh);
            }
        }
    }
    /* write partials: D rows mrow+(lane>>2)(+8), cols ncol+nt*8+(lane&3)*2 */
    float* gp = g_gpart + (size_t)blockIdx.x * 4096;
    const int r0 = mrow + (lane >> 2);
#pragma unroll
    for (int nt = 0; nt < 4; ++nt) {
        const int c0 = ncol + nt * 8 + (lane & 3) * 2;
        gp[r0 * 64 + c0]           = acc[nt][0];
        gp[r0 * 64 + c0 + 1]       = acc[nt][1];
        gp[(r0 + 8) * 64 + c0]     = acc[nt][2];
        gp[(r0 + 8) * 64 + c0 + 1] = acc[nt][3];
    }
}

/* ================= reduce h1 gram + colsum =========================== */
__global__ void gram2fin_kernel() {
    __shared__ float red[64][4];
    const int t = threadIdx.x;
    const int e = t >> 2, sl = t & 3;
    if (blockIdx.x == 64) {
        float a = 0.f;
        for (int i = sl; i < 8192; i += 4) a += g_colpart[(size_t)e * 8192 + i];
        red[e][sl] = a;
        __syncthreads();
        if (sl == 0)
            g_h1colsum[e] = red[e][0] + red[e][1] + red[e][2] + red[e][3];
        return;
    }
    const int ge = blockIdx.x * 64 + e;
    float a = 0.f;
    for (int i = sl; i < 640; i += 4) a += g_gpart[(size_t)i * 4096 + ge];
    red[e][sl] = a;
    __syncthreads();
    if (sl == 0)
        g_gram[ge] = red[e][0] + red[e][1] + red[e][2] + red[e][3];
}

/* ================= BN2 stats from h1 Gram ============================ */
__global__ void bn2fin_kernel() {
    const int o = blockIdx.x;
    const int i = threadIdx.x;
    __shared__ float w[64], rq[64], rm[64];
    w[i] = g_w2t[i * 128 + o];
    __syncthreads();
    float qi = 0.f;
    const float* Gi = g_gram + i * 64;
#pragma unroll 8
    for (int j = 0; j < 64; ++j) qi = fmaf(Gi[j], w[j], qi);
    rq[i] = qi * w[i];
    rm[i] = w[i] * g_h1colsum[i];
    __syncthreads();
    for (int s = 32; s > 0; s >>= 1) {
        if (i < s) { rq[i] += rq[i + s]; rm[i] += rm[i + s]; }
        __syncthreads();
    }
    if (i == 0) {
        const float invM = 1.f / (float)M1;
        float mu = rm[0] * invM;
        float var = rq[0] * invM - mu * mu;
        g_mu[64 + o] = mu;
        g_rs[64 + o] = rsqrtf(var + EPSB);
    }
}

/* ================= GEMM2 via mma.sync bf16 hi/lo + pool ============== */
#define G2_ROWB   144
#define G2_OFF_F6   0
#define G2_OFF_WHI  5120
#define G2_OFF_WLO  (G2_OFF_WHI + 128 * G2_ROWB)
#define G2_OFF_BHI  (G2_OFF_WLO + 128 * G2_ROWB)
#define G2_OFF_BLO  (G2_OFF_BHI + 160 * G2_ROWB)
#define G2_OFF_SLAB (G2_OFF_BLO + 160 * G2_ROWB)
#define G2_SLABW    (16 * 44 * 4)
#define G2_SMEM     (G2_OFF_SLAB + 8 * G2_SLABW)

__global__ __launch_bounds__(256) void gemm2pool_hmma(
        const float* __restrict__ x,  const float* __restrict__ W1,
        const float* __restrict__ g1, const float* __restrict__ b1,
        const float* __restrict__ g2, const float* __restrict__ b2v) {
    extern __shared__ __align__(16) char smem[];
    const int t = threadIdx.x;
    const int w = t >> 5, lane = t & 31;
    const uint32_t sbase = smem_u32(smem);
    float* f6 = (float*)(smem + G2_OFF_F6);

    if (t < 160) {
        int m = blockIdx.x * 160 + t;
        int p = m / KNB, b_ = p >> 12, n_ = p & (NN - 1);
        const float* xb = x + b_ * 3 * NN;
        int nb = g_idx[m];
        float cx = xb[n_], cy = xb[NN + n_], cz = xb[2 * NN + n_];
        f6[t * 8 + 0] = xb[nb] - cx;
        f6[t * 8 + 1] = xb[NN + nb] - cy;
        f6[t * 8 + 2] = xb[2 * NN + nb] - cz;
        f6[t * 8 + 3] = cx; f6[t * 8 + 4] = cy; f6[t * 8 + 5] = cz;
    }
#pragma unroll
    for (int l = 0; l < 4; ++l) {
        int q = t + 256 * l;
        int r = q >> 3, c16 = q & 7;
        *(uint4*)(smem + G2_OFF_WHI + r * G2_ROWB + c16 * 16) = ((const uint4*)g_w2hi)[q];
        *(uint4*)(smem + G2_OFF_WLO + r * G2_ROWB + c16 * 16) = ((const uint4*)g_w2lo)[q];
    }
    __syncthreads();

    {
        const int c  = t & 63;
        const int eg = t >> 6;
        float wr[6];
#pragma unroll
        for (int j = 0; j < 6; ++j) wr[j] = W1[c * 6 + j];
        const float mu = g_mu[c], rsv = g_rs[c], gg = g1[c], bb = b1[c];
#pragma unroll 4
        for (int i = 0; i < 40; ++i) {
            const int e = eg + i * 4;
            const float* f = f6 + e * 8;
            float y = wr[0] * f[0];
            y = fmaf(wr[1], f[1], y);
            y = fmaf(wr[2], f[2], y);
            y = fmaf(wr[3], f[3], y);
            y = fmaf(wr[4], f[4], y);
            y = fmaf(wr[5], f[5], y);
            float h = fmaxf(fmaf((y - mu) * rsv, gg, bb), 0.f);
            __nv_bfloat16 hi = __float2bfloat16(h);
            __nv_bfloat16 lo = __float2bfloat16(h - __bfloat162float(hi));
            *(__nv_bfloat16*)(smem + G2_OFF_BHI + e * G2_ROWB + c * 2) = hi;
            *(__nv_bfloat16*)(smem + G2_OFF_BLO + e * G2_ROWB + c * 2) = lo;
        }
    }
    __syncthreads();

    const int cbase = w * 16;
    uint32_t ahi[4][4], alo[4][4];
    {
        const uint32_t arow = (uint32_t)(cbase + (lane & 15)) * G2_ROWB
                            + ((lane >> 4) & 1) * 16;
#pragma unroll
        for (int kc = 0; kc < 4; ++kc) {
            ldsm_x4(ahi[kc], sbase + G2_OFF_WHI + arow + kc * 32);
            ldsm_x4(alo[kc], sbase + G2_OFF_WLO + arow + kc * 32);
        }
    }

    const int pch = cbase + (lane & 15);
    const float mu2 = g_mu[64 + pch], rs2 = g_rs[64 + pch];
    const float gg2 = g2[pch], bb2 = b2v[pch];
    float* slab = (float*)(smem + G2_OFF_SLAB + w * G2_SLABW);

#pragma unroll
    for (int grp = 0; grp < 4; ++grp) {
        float D[5][4];
#pragma unroll
        for (int nt = 0; nt < 5; ++nt)
#pragma unroll
            for (int j = 0; j < 4; ++j) D[nt][j] = 0.f;

#pragma unroll
        for (int nt = 0; nt < 5; ++nt) {
            const int ebase = grp * 40 + nt * 8;
            const uint32_t brow = (uint32_t)(ebase + (lane & 7)) * G2_ROWB
                                + ((lane >> 3) & 1) * 16;
#pragma unroll
            for (int kc = 0; kc < 4; ++kc) {
                uint32_t bh[2], bl[2];
                ldsm_x2(bh, sbase + G2_OFF_BHI + brow + kc * 32);
                ldsm_x2(bl, sbase + G2_OFF_BLO + brow + kc * 32);
                mma_bf16(D[nt], ahi[kc], bh);
                mma_bf16(D[nt], ahi[kc], bl);
                mma_bf16(D[nt], alo[kc], bh);
            }
        }
        {
            const int r0 = lane >> 2;
            const int c0 = 2 * (lane & 3);
#pragma unroll
            for (int nt = 0; nt < 5; ++nt) {
                const int col = nt * 8 + c0;
                slab[r0 * 44 + col]           = D[nt][0];
                slab[r0 * 44 + col + 1]       = D[nt][1];
                slab[(r0 + 8) * 44 + col]     = D[nt][2];
                slab[(r0 + 8) * 44 + col + 1] = D[nt][3];
            }
        }
        __syncwarp();
        {
            const int ch = lane & 15;
            const int ph = lane >> 4;
            const float* row = slab + ch * 44 + ph * 20;
            float h[20], hmax = 0.f;
#pragma unroll
            for (int k = 0; k < 20; ++k) {
                float y = row[k];
                h[k] = fmaxf(fmaf((y - mu2) * rs2, gg2, bb2), 0.f);
                hmax = fmaxf(hmax, h[k]);
            }
            float se = 0.f, sw = 0.f;
#pragma unroll
            for (int k = 0; k < 20; ++k) {
                float e = __expf(h[k] - hmax);
                se += e;
                sw = fmaf(e, h[k], sw);
            }
            const int p = blockIdx.x * 8 + grp * 2 + ph;
            g_cat[(size_t)p * 192 + 64 + pch] = sw / se;
        }
        __syncwarp();
    }
}

/* ================= cat Gram (192x192) + colsum ======================= */
__global__ __launch_bounds__(256) void catgram_kernel() {
    __shared__ float sm[16][196];
    const int t = threadIdx.x;
    const int i16 = t & 15, j16 = t >> 4;

    double acc[12][6];
#pragma unroll
    for (int i = 0; i < 12; ++i)
#pragma unroll
        for (int j = 0; j < 6; ++j) acc[i][j] = 0.0;
    float cs[12];
#pragma unroll
    for (int u = 0; u < 12; ++u) cs[u] = 0.f;

    for (int c = 0; c < 16; ++c) {
        const int rowbase = blockIdx.x * 256 + c * 16;
#pragma unroll
        for (int l = 0; l < 3; ++l) {
            int q = t + 256 * l;
            int r = q / 48, cq = (q % 48) * 4;
            *(float4*)&sm[r][cq] =
                *(const float4*)(g_cat + (size_t)(rowbase + r) * 192 + cq);
        }
        __syncthreads();
#pragma unroll 4
        for (int r = 0; r < 16; ++r) {
            float a[12];
#pragma unroll
            for (int u = 0; u < 6; ++u) {
                float2 pv = *(const float2*)&sm[r][i16 * 12 + 2 * u];
                a[2 * u] = pv.x; a[2 * u + 1] = pv.y;
            }
            double bd[6];
#pragma unroll
            for (int u = 0; u < 6; ++u)
                bd[u] = *(const double*)&sm[r][j16 * 12 + 2 * u];
#pragma unroll
            for (int i = 0; i < 12; ++i) {
                double a2 = pack2(a[i], a[i]);
#pragma unroll
                for (int j = 0; j < 6; ++j)
                    acc[i][j] = ffma2(a2, bd[j], acc[i][j]);
            }
            if (j16 == 0) {
#pragma unroll
                for (int u = 0; u < 12; ++u) cs[u] += a[u];
            }
        }
        __syncthreads();
    }
    float* cp = g_cpart + (size_t)blockIdx.x * 36864;
#pragma unroll
    for (int i = 0; i < 12; ++i) {
        float* row = cp + (i16 * 12 + i) * 192 + j16 * 12;
#pragma unroll
        for (int j = 0; j < 6; ++j) {
            float2 v = unpack2(acc[i][j]);
            *(float2*)(row + 2 * j) = v;
        }
    }
    if (j16 == 0) {
#pragma unroll
        for (int u = 0; u < 12; ++u)
            g_cspart[blockIdx.x * 192 + i16 * 12 + u] = cs[u];
    }
}

/* ================= reduce cat gram + colsum ========================== */
__global__ void gram3fin_kernel() {
    const int t = threadIdx.x;
    if (blockIdx.x == 144) {
        if (t < 192) {
            float a = 0.f;
            for (int p = 0; p < 128; ++p) a += g_cspart[p * 192 + t];
            g_catsum[t] = a;
        }
        return;
    }
    const int e = blockIdx.x * 256 + t;
    float a = 0.f;
    for (int p = 0; p < 128; ++p) a += g_cpart[(size_t)p * 36864 + e];
    g_cgram[e] = a;
}

/* ================= BN3 stats from cat Gram =========================== */
__global__ void bn3fin_kernel() {
    const int o = blockIdx.x;
    const int i = threadIdx.x;
    __shared__ float w[192], rq[192], rm[192];
    w[i] = g_w3t[i * 256 + o];
    __syncthreads();
    float qi = 0.f;
    const float* Gi = g_cgram + i * 192;
#pragma unroll 8
    for (int j = 0; j < 192; ++j) qi = fmaf(Gi[j], w[j], qi);
    rq[i] = qi * w[i];
    rm[i] = w[i] * g_catsum[i];
    __syncthreads();
    for (int s = 96; s >= 3; s >>= 1) {
        if (i < s) { rq[i] += rq[i + s]; rm[i] += rm[i + s]; }
        __syncthreads();
    }
    if (i == 0) {
        const float invN = 1.f / (float)NPTS;
        float mu = (rm[0] + rm[1] + rm[2]) * invN;
        float var = (rq[0] + rq[1] + rq[2]) * invN - mu * mu;
        g_mu[192 + o] = mu;
        g_rs[192 + o] = rsqrtf(var + EPSB);
    }
}

/* ================= GEMM3 via HMMA hi/lo + BN3 + transposed out ======= */
/* 128 rows x 128 chans per block, K=192 in 3 chunks of 64.              */
/* A = cat rows bf16-split on load, B = W3 [o][k] bf16 hi/lo.            */
#define G3_ROWB 144
#define G3_OFF_AHI 0
#define G3_OFF_ALO (G3_OFF_AHI + 128 * G3_ROWB)
#define G3_OFF_BHI (G3_OFF_ALO + 128 * G3_ROWB)
#define G3_OFF_BLO (G3_OFF_BHI + 128 * G3_ROWB)
#define G3_SMEM    (G3_OFF_BLO + 128 * G3_ROWB)   /* 73728; slab 67584 fits */

__global__ __launch_bounds__(256) void gemm3out_hmma(
        const float* __restrict__ g3, const float* __restrict__ b3,
        float* __restrict__ out) {
    extern __shared__ __align__(16) char smem[];
    const int t = threadIdx.x;
    const int w = t >> 5, lane = t & 31;
    const uint32_t sbase = smem_u32(smem);
    const int mbase = blockIdx.x * 128;
    const int nbase = blockIdx.y * 128;
    const int mrow = (w & 3) * 32;
    const int ncol = (w >> 2) * 64;

    float acc[2][8][4];
#pragma unroll
    for (int mt = 0; mt < 2; ++mt)
#pragma unroll
        for (int nt = 0; nt < 8; ++nt)
#pragma unroll
            for (int j = 0; j < 4; ++j) acc[mt][nt][j] = 0.f;

#pragma unroll
    for (int kc = 0; kc < 3; ++kc) {
        /* A: cat rows -> bf16 hi/lo tiles */
#pragma unroll
        for (int l = 0; l < 8; ++l) {
            int q = t + 256 * l;
            int r = q >> 4, kq = (q & 15) * 4;
            float4 v = *(const float4*)(g_cat + (size_t)(mbase + r) * 192
                                        + kc * 64 + kq);
            uint2 hi, lo;
            split4(v, &hi, &lo);
            *(uint2*)(smem + G3_OFF_AHI + r * G3_ROWB + kq * 2) = hi;
            *(uint2*)(smem + G3_OFF_ALO + r * G3_ROWB + kq * 2) = lo;
        }
        /* B: W3 bf16 hi/lo 16B chunks */
#pragma unroll
        for (int l = 0; l < 4; ++l) {
            int q = t + 256 * l;
            int r = q >> 3, c16 = q & 7;
            const char* srch = (const char*)g_w3hi
                + (size_t)(nbase + r) * 384 + kc * 128 + c16 * 16;
            const char* srcl = (const char*)g_w3lo
                + (size_t)(nbase + r) * 384 + kc * 128 + c16 * 16;
            *(uint4*)(smem + G3_OFF_BHI + r * G3_ROWB + c16 * 16) = *(const uint4*)srch;
            *(uint4*)(smem + G3_OFF_BLO + r * G3_ROWB + c16 * 16) = *(const uint4*)srcl;
        }
        __syncthreads();

#pragma unroll
        for (int ks = 0; ks < 4; ++ks) {
            uint32_t ah[2][4], al[2][4];
#pragma unroll
            for (int mt = 0; mt < 2; ++mt) {
                const uint32_t aoff =
                    (uint32_t)(mrow + mt * 16 + (lane & 15)) * G3_ROWB
                    + ((lane >> 4) & 1) * 16 + ks * 32;
                ldsm_x4(ah[mt], sbase + G3_OFF_AHI + aoff);
                ldsm_x4(al[mt], sbase + G3_OFF_ALO + aoff);
            }
#pragma unroll
            for (int nt = 0; nt < 8; ++nt) {
                const uint32_t boff =
                    (uint32_t)(ncol + nt * 8 + (lane & 7)) * G3_ROWB
                    + ((lane >> 3) & 1) * 16 + ks * 32;
                uint32_t bh[2], bl[2];
                ldsm_x2(bh, sbase + G3_OFF_BHI + boff);
                ldsm_x2(bl, sbase + G3_OFF_BLO + boff);
#pragma unroll
                for (int mt = 0; mt < 2; ++mt) {
                    mma_bf16(acc[mt][nt], ah[mt], bh);
                    mma_bf16(acc[mt][nt], ah[mt], bl);
                    mma_bf16(acc[mt][nt], al[mt], bh);
                }
            }
        }
        __syncthreads();
    }

    /* stage D chan-major: slab[chan_local][row_local], stride 132 */
    float* slab = (float*)smem;
#pragma unroll
    for (int mt = 0; mt < 2; ++mt) {
        const int r = mrow + mt * 16 + (lane >> 2);
#pragma unroll
        for (int nt = 0; nt < 8; ++nt) {
            const int cl = ncol + nt * 8 + (lane & 3) * 2;
            slab[cl * 132 + r]           = acc[mt][nt][0];
            slab[(cl + 1) * 132 + r]     = acc[mt][nt][1];
            slab[cl * 132 + r + 8]       = acc[mt][nt][2];
            slab[(cl + 1) * 132 + r + 8] = acc[mt][nt][3];
        }
    }
    __syncthreads();

    /* BN3 + ReLU + transposed coalesced write */
    const int b = mbase >> 12;
    const int nloc = mbase & (NN - 1);
    const int cl = t >> 1;
    const int half = t & 1;
    const int o = nbase + cl;
    const float mu = g_mu[192 + o], rsv = g_rs[192 + o];
    const float gg = g3[o], bb = b3[o];
    const float* srow = slab + cl * 132 + half * 64;
    float* op = out + ((size_t)b * 256 + o) * NN + nloc + half * 64;
#pragma unroll
    for (int j = 0; j < 16; ++j) {
        float4 v = *(const float4*)(srow + j * 4);
        float4 r;
        r.x = fmaxf(fmaf((v.x - mu) * rsv, gg, bb), 0.f);
        r.y = fmaxf(fmaf((v.y - mu) * rsv, gg, bb), 0.f);
        r.z = fmaxf(fmaf((v.z - mu) * rsv, gg, bb), 0.f);
        r.w = fmaxf(fmaf((v.w - mu) * rsv, gg, bb), 0.f);
        *(float4*)(op + j * 4) = r;
    }
}

/* ================= launcher ========================================== */
extern "C" void kernel_launch(void* const* d_in, const int* in_sizes, int n_in,
                              void* d_out, int out_size) {
    const float* x  = (const float*)d_in[0];
    const float* W1 = (const float*)d_in[1];
    const float* g1 = (const float*)d_in[2];
    const float* b1 = (const float*)d_in[3];
    const float* W2 = (const float*)d_in[4];
    const float* g2 = (const float*)d_in[5];
    const float* b2 = (const float*)d_in[6];
    const float* W3 = (const float*)d_in[7];
    const float* g3 = (const float*)d_in[8];
    const float* b3 = (const float*)d_in[9];
    float* out = (float*)d_out;

    cudaFuncSetAttribute(gemm2pool_hmma,
                         cudaFuncAttributeMaxDynamicSharedMemorySize, G2_SMEM);
    cudaFuncSetAttribute(gemm3out_hmma,
                         cudaFuncAttributeMaxDynamicSharedMemorySize, G3_SMEM);

    prep_kernel<<<192, 256>>>(W2, W3);
    knn_kernel<<<dim3(BB, NN / 256), 256>>>(x);

    fgram_kernel<<<640, 256>>>(x);
    bn1fin_kernel<<<1, 256>>>(W1);

    h1pool_kernel<<<NPTS / 4, 256>>>(x, W1, g1, b1);

    h1gram_hmma<<<640, 256>>>(x, W1, g1, b1);
    gram2fin_kernel<<<65, 256>>>();
    bn2fin_kernel<<<128, 64>>>();

    gemm2pool_hmma<<<M1 / 160, 256, G2_SMEM>>>(x, W1, g1, b1, g2, b2);

    catgram_kernel<<<128, 256>>>();
    gram3fin_kernel<<<145, 256>>>();
    bn3fin_kernel<<<256, 192>>>();

    gemm3out_hmma<<<dim3(NPTS / 128, 2), 256, G3_SMEM>>>(g3, b3, out);

    (void)in_sizes; (void)n_in; (void)out_size;
}